// round 1
// baseline (speedup 1.0000x reference)
#include <cuda_runtime.h>
#include <cstdint>

#define Hh   744
#define HP   768
#define Bb   256
#define Tt   256
#define Cc   16
#define WIN  800
#define TB   (Tt*Bb)          // 65536
#define OUTT (Tt - 2*Cc)      // 224
#define OUTW (2*Hh)           // 1488

// ---------------- scratch (device globals; no runtime allocation) ----------------
__device__ float g_Wi[2][3][HP][HP];      // tf32-rounded, zero-padded input weights
__device__ float g_Wh[2][3][HP][HP];      // tf32-rounded, zero-padded recurrent weights
__device__ float g_bi[2][3][HP];
__device__ float g_bh[2][3][HP];
__device__ float g_X [TB][HP];            // tf32-rounded x, row = t*Bb + b
__device__ float g_GI[2][3][TB][HP];      // input projections (incl bih)
__device__ float g_h [2][2][Bb][HP];      // [parity][dir][b][j], fp32

// ---------------- helpers ----------------
__device__ __forceinline__ float tf32r(float x) {
    uint32_t u;
    asm("cvt.rna.tf32.f32 %0, %1;" : "=r"(u) : "f"(x));
    return __uint_as_float(u);
}
__device__ __forceinline__ float sigf(float x) {
    return 1.0f / (1.0f + __expf(-x));
}
__device__ __forceinline__ float tanh_fast(float x) {
    x = fminf(15.0f, fmaxf(-15.0f, x));
    float e = __expf(2.0f * x);
    return (e - 1.0f) / (e + 1.0f);
}
__device__ __forceinline__ void mma_tf32(float* c, const uint32_t* a, const uint32_t* b) {
    asm volatile(
        "mma.sync.aligned.m16n8k8.row.col.f32.tf32.tf32.f32 "
        "{%0,%1,%2,%3},{%4,%5,%6,%7},{%8,%9},{%0,%1,%2,%3};\n"
        : "+f"(c[0]), "+f"(c[1]), "+f"(c[2]), "+f"(c[3])
        : "r"(a[0]), "r"(a[1]), "r"(a[2]), "r"(a[3]), "r"(b[0]), "r"(b[1]));
}

// ---------------- prep kernels ----------------
__global__ void prep_w(const float* __restrict__ Wih, const float* __restrict__ Whh,
                       const float* __restrict__ bih, const float* __restrict__ bhh, int d) {
    int idx = blockIdx.x * blockDim.x + threadIdx.x;
    const int total = 3 * HP * HP;
    if (idx < total) {
        int g = idx / (HP * HP);
        int rem = idx % (HP * HP);
        int j = rem / HP;
        int k = rem % HP;
        float wi = 0.0f, wh = 0.0f;
        if (j < Hh && k < Hh) {
            wi = tf32r(Wih[(size_t)(g * Hh + j) * Hh + k]);
            wh = tf32r(Whh[(size_t)(g * Hh + j) * Hh + k]);
        }
        g_Wi[d][g][j][k] = wi;
        g_Wh[d][g][j][k] = wh;
    }
    if (idx < 3 * HP) {
        int g = idx / HP, j = idx % HP;
        float bi = 0.0f, bh = 0.0f;
        if (j < Hh) { bi = bih[g * Hh + j]; bh = bhh[g * Hh + j]; }
        g_bi[d][g][j] = bi;
        g_bh[d][g][j] = bh;
    }
}

__global__ void prep_x(const float* __restrict__ win) {
    int idx = blockIdx.x * blockDim.x + threadIdx.x;
    const int total = TB * (HP / 4);
    if (idx >= total) return;
    int row = idx / (HP / 4);
    int kq  = idx % (HP / 4);
    int k = kq * 4;
    int t = row / Bb, b = row % Bb;
    float4 v = make_float4(0.f, 0.f, 0.f, 0.f);
    if (k < Hh) {
        v = *(const float4*)(win + (size_t)b * Tt * WIN + (size_t)t * WIN + k);
        v.x = tf32r(v.x); v.y = tf32r(v.y); v.z = tf32r(v.z); v.w = tf32r(v.w);
    }
    *(float4*)&g_X[row][k] = v;
}

__global__ void zero_h() {
    int idx = blockIdx.x * blockDim.x + threadIdx.x;
    const int total = 2 * 2 * Bb * HP;
    if (idx < total) ((float*)g_h)[idx] = 0.0f;
}

// ---------------- K1: GI = X @ Wih^T + bih  (per dir, per gate plane) ----------------
// grid: (HP/64 = 12, TB/128 = 512, 6 = dir*3+gate), 256 threads
__global__ void k_gi() {
    __shared__ float As[128][36];
    __shared__ float Bs[64][36];

    const int tid  = threadIdx.x;
    const int lane = tid & 31;
    const int w    = tid >> 5;
    const int grp  = lane >> 2;
    const int tg   = lane & 3;
    const int wm   = w >> 1;   // 0..3 -> row offset *32
    const int wn   = w & 1;    // 0..1 -> col offset *32

    const int j0   = blockIdx.x * 64;
    const int row0 = blockIdx.y * 128;
    const int dg   = blockIdx.z;
    const int d    = dg / 3, g = dg % 3;

    const float* __restrict__ Ag = &g_X[row0][0];
    const float* __restrict__ Bg = &g_Wi[d][g][j0][0];

    float acc[32];
#pragma unroll
    for (int i = 0; i < 32; i++) acc[i] = 0.0f;

    for (int kt = 0; kt < HP / 32; kt++) {
        const int k0 = kt * 32;
#pragma unroll
        for (int i = 0; i < 4; i++) {           // A: 128x32 = 1024 float4 / 256 thr
            int li = tid + i * 256;
            int r = li >> 3, kq = li & 7;
            float4 v = *(const float4*)(Ag + (size_t)r * HP + k0 + kq * 4);
            *(float4*)&As[r][kq * 4] = v;
        }
#pragma unroll
        for (int i = 0; i < 2; i++) {           // B: 64x32 = 512 float4
            int li = tid + i * 256;
            int r = li >> 3, kq = li & 7;
            float4 v = *(const float4*)(Bg + (size_t)r * HP + k0 + kq * 4);
            *(float4*)&Bs[r][kq * 4] = v;
        }
        __syncthreads();

#pragma unroll
        for (int kk = 0; kk < 4; kk++) {
            const int kb = kk * 8;
            uint32_t af[2][4];
#pragma unroll
            for (int mi = 0; mi < 2; mi++) {
                int r = wm * 32 + mi * 16 + grp;
                af[mi][0] = __float_as_uint(As[r][kb + tg]);
                af[mi][1] = __float_as_uint(As[r + 8][kb + tg]);
                af[mi][2] = __float_as_uint(As[r][kb + tg + 4]);
                af[mi][3] = __float_as_uint(As[r + 8][kb + tg + 4]);
            }
#pragma unroll
            for (int ni = 0; ni < 4; ni++) {
                int jr = wn * 32 + ni * 8 + grp;
                uint32_t bf[2] = { __float_as_uint(Bs[jr][kb + tg]),
                                   __float_as_uint(Bs[jr][kb + tg + 4]) };
#pragma unroll
                for (int mi = 0; mi < 2; mi++)
                    mma_tf32(&acc[(mi * 4 + ni) * 4], af[mi], bf);
            }
        }
        __syncthreads();
    }

    // epilogue: add bih, store
    float* __restrict__ GIp = &g_GI[d][g][0][0];
    const float* __restrict__ bip = &g_bi[d][g][0];
#pragma unroll
    for (int mi = 0; mi < 2; mi++) {
#pragma unroll
        for (int ni = 0; ni < 4; ni++) {
            int r = row0 + wm * 32 + mi * 16 + grp;
            int j = j0 + wn * 32 + ni * 8 + tg * 2;
            float b0 = bip[j], b1 = bip[j + 1];
            float* a = &acc[(mi * 4 + ni) * 4];
            GIp[(size_t)r * HP + j]           = a[0] + b0;
            GIp[(size_t)r * HP + j + 1]       = a[1] + b1;
            GIp[(size_t)(r + 8) * HP + j]     = a[2] + b0;
            GIp[(size_t)(r + 8) * HP + j + 1] = a[3] + b1;
        }
    }
}

// ---------------- K2: one GRU timestep, both directions ----------------
// grid: (HP/32 = 24, Bb/64 = 4, 2 dirs), 128 threads
__global__ void k_step(const float* __restrict__ win, float* __restrict__ out, int t) {
    __shared__ float As[64][36];
    __shared__ float Bs[3][32][36];

    const int tid  = threadIdx.x;
    const int lane = tid & 31;
    const int w    = tid >> 5;
    const int grp  = lane >> 2;
    const int tg   = lane & 3;
    const int wm   = w >> 1;   // 0..1 -> row offset *32
    const int wj   = w & 1;    // 0..1 -> col offset *16

    const int j0 = blockIdx.x * 32;
    const int m0 = blockIdx.y * 64;
    const int d  = blockIdx.z;
    const int p  = t & 1;

    const float* __restrict__ hA = &g_h[p][d][m0][0];

    float acc[3][16];
#pragma unroll
    for (int g = 0; g < 3; g++)
#pragma unroll
        for (int i = 0; i < 16; i++) acc[g][i] = 0.0f;

    for (int kt = 0; kt < HP / 32; kt++) {
        const int k0 = kt * 32;
#pragma unroll
        for (int i = 0; i < 4; i++) {           // A(h): 64x32 = 512 float4 / 128 thr
            int li = tid + i * 128;
            int r = li >> 3, kq = li & 7;
            float4 v = *(const float4*)(hA + (size_t)r * HP + k0 + kq * 4);
            v.x = tf32r(v.x); v.y = tf32r(v.y); v.z = tf32r(v.z); v.w = tf32r(v.w);
            *(float4*)&As[r][kq * 4] = v;
        }
#pragma unroll
        for (int i = 0; i < 6; i++) {           // B: 3 gates x 32x32 = 768 float4
            int li = tid + i * 128;
            int g = li >> 8, rem = li & 255;
            int r = rem >> 3, kq = rem & 7;
            float4 v = *(const float4*)(&g_Wh[d][g][j0 + r][k0 + kq * 4]);
            *(float4*)&Bs[g][r][kq * 4] = v;
        }
        __syncthreads();

#pragma unroll
        for (int kk = 0; kk < 4; kk++) {
            const int kb = kk * 8;
            uint32_t af[2][4];
#pragma unroll
            for (int mi = 0; mi < 2; mi++) {
                int r = wm * 32 + mi * 16 + grp;
                af[mi][0] = __float_as_uint(As[r][kb + tg]);
                af[mi][1] = __float_as_uint(As[r + 8][kb + tg]);
                af[mi][2] = __float_as_uint(As[r][kb + tg + 4]);
                af[mi][3] = __float_as_uint(As[r + 8][kb + tg + 4]);
            }
#pragma unroll
            for (int g = 0; g < 3; g++) {
#pragma unroll
                for (int ji = 0; ji < 2; ji++) {
                    int jr = wj * 16 + ji * 8 + grp;
                    uint32_t bf[2] = { __float_as_uint(Bs[g][jr][kb + tg]),
                                       __float_as_uint(Bs[g][jr][kb + tg + 4]) };
#pragma unroll
                    for (int mi = 0; mi < 2; mi++)
                        mma_tf32(&acc[g][(mi * 2 + ji) * 4], af[mi], bf);
                }
            }
        }
        __syncthreads();
    }

    // ---- fused GRU epilogue ----
    const bool doOut = (t >= Cc) && (t < Tt - Cc);
    const int  xt    = (d == 0) ? t : (Tt - 1 - t);
    const size_t PLANE = (size_t)TB * HP;
    const float* __restrict__ GI0 = &g_GI[d][0][0][0];
    const float* __restrict__ bh0 = &g_bh[d][0][0];
    const float* __restrict__ hin = &g_h[p][d][0][0];
    float* __restrict__ hout      = &g_h[p ^ 1][d][0][0];

#pragma unroll
    for (int mi = 0; mi < 2; mi++) {
#pragma unroll
        for (int ji = 0; ji < 2; ji++) {
            const int fidx = mi * 2 + ji;
            const int cc = j0 + wj * 16 + ji * 8 + tg * 2;
            const float br0 = bh0[cc],            br1 = bh0[cc + 1];
            const float bz0 = bh0[HP + cc],       bz1 = bh0[HP + cc + 1];
            const float bn0 = bh0[2 * HP + cc],   bn1 = bh0[2 * HP + cc + 1];
#pragma unroll
            for (int half = 0; half < 2; half++) {
                const int b = m0 + wm * 32 + mi * 16 + grp + half * 8;
                const float aR0 = acc[0][fidx * 4 + half * 2], aR1 = acc[0][fidx * 4 + half * 2 + 1];
                const float aZ0 = acc[1][fidx * 4 + half * 2], aZ1 = acc[1][fidx * 4 + half * 2 + 1];
                const float aN0 = acc[2][fidx * 4 + half * 2], aN1 = acc[2][fidx * 4 + half * 2 + 1];

                const size_t gio = (size_t)(xt * Bb + b) * HP + cc;
                const float gr0 = GI0[gio],              gr1 = GI0[gio + 1];
                const float gz0 = GI0[PLANE + gio],      gz1 = GI0[PLANE + gio + 1];
                const float gn0 = GI0[2 * PLANE + gio],  gn1 = GI0[2 * PLANE + gio + 1];

                const float ho0 = hin[(size_t)b * HP + cc];
                const float ho1 = hin[(size_t)b * HP + cc + 1];

                const float r0 = sigf(gr0 + aR0 + br0);
                const float r1 = sigf(gr1 + aR1 + br1);
                const float z0 = sigf(gz0 + aZ0 + bz0);
                const float z1 = sigf(gz1 + aZ1 + bz1);
                const float n0 = tanh_fast(gn0 + r0 * (aN0 + bn0));
                const float n1 = tanh_fast(gn1 + r1 * (aN1 + bn1));
                const float h0 = (1.0f - z0) * n0 + z0 * ho0;
                const float h1 = (1.0f - z1) * n1 + z1 * ho1;

                hout[(size_t)b * HP + cc]     = h0;
                hout[(size_t)b * HP + cc + 1] = h1;

                if (doOut && cc < Hh) {
                    const size_t xo = (size_t)b * Tt * WIN + (size_t)xt * WIN + cc;
                    const size_t oo = (size_t)b * (OUTT * OUTW) + (size_t)(t - Cc) * OUTW + d * Hh + cc;
                    out[oo]     = h0 + win[xo];
                    out[oo + 1] = h1 + win[xo + 1];
                }
            }
        }
    }
}

// ---------------- launch ----------------
extern "C" void kernel_launch(void* const* d_in, const int* in_sizes, int n_in,
                              void* d_out, int out_size) {
    const float* windows = (const float*)d_in[0];
    const float* Wih_f   = (const float*)d_in[1];
    const float* Whh_f   = (const float*)d_in[2];
    const float* bih_f   = (const float*)d_in[3];
    const float* bhh_f   = (const float*)d_in[4];
    const float* Wih_b   = (const float*)d_in[5];
    const float* Whh_b   = (const float*)d_in[6];
    const float* bih_b   = (const float*)d_in[7];
    const float* bhh_b   = (const float*)d_in[8];
    float* out = (float*)d_out;

    const int wthreads = 256;
    const int wtotal = 3 * HP * HP;
    prep_w<<<(wtotal + wthreads - 1) / wthreads, wthreads>>>(Wih_f, Whh_f, bih_f, bhh_f, 0);
    prep_w<<<(wtotal + wthreads - 1) / wthreads, wthreads>>>(Wih_b, Whh_b, bih_b, bhh_b, 1);

    const int xtotal = TB * (HP / 4);
    prep_x<<<(xtotal + 255) / 256, 256>>>(windows);

    const int htotal = 2 * 2 * Bb * HP;
    zero_h<<<(htotal + 255) / 256, 256>>>();

    k_gi<<<dim3(HP / 64, TB / 128, 6), 256>>>();

    for (int t = 0; t < Tt; t++)
        k_step<<<dim3(HP / 32, Bb / 64, 2), 128>>>(windows, out, t);
}

// round 2
// speedup vs baseline: 1.1329x; 1.1329x over previous
#include <cuda_runtime.h>
#include <cstdint>

#define Hh   744
#define HP   768
#define Bb   256
#define Tt   256
#define Cc   16
#define WIN  800
#define TB   (Tt*Bb)          // 65536
#define OUTT (Tt - 2*Cc)      // 224
#define OUTW (2*Hh)           // 1488

#define NJT    48             // j-tiles per dir (768/16)
#define JT     16             // j per tile
#define NCTA   (2*NJT)        // 96 persistent CTAs
#define WS_STRIDE 772         // 768 + 4 pad (bank-conflict-free)
#define AS_STRIDE 36          // 32 + 4 pad

// ---------------- scratch (device globals; no runtime allocation) ----------------
__device__ float g_Wi[2][3][HP][HP];
__device__ float g_Wh[2][3][HP][HP];
__device__ float g_bi[2][3][HP];
__device__ float g_bh[2][3][HP];
__device__ float g_X [TB][HP];            // tf32-rounded x, row = t*Bb + b
__device__ float g_GI[2][3][TB][HP];      // input projections (incl bih)
__device__ float g_h [2][2][Bb][HP];      // [parity][dir][b][j]
__device__ unsigned g_bar;

// ---------------- helpers ----------------
__device__ __forceinline__ float tf32r(float x) {
    uint32_t u;
    asm("cvt.rna.tf32.f32 %0, %1;" : "=r"(u) : "f"(x));
    return __uint_as_float(u);
}
__device__ __forceinline__ uint32_t tf32u(float x) {
    uint32_t u;
    asm("cvt.rna.tf32.f32 %0, %1;" : "=r"(u) : "f"(x));
    return u;
}
__device__ __forceinline__ float sigf(float x) { return 1.0f / (1.0f + __expf(-x)); }
__device__ __forceinline__ float tanh_fast(float x) {
    x = fminf(15.0f, fmaxf(-15.0f, x));
    float e = __expf(2.0f * x);
    return (e - 1.0f) / (e + 1.0f);
}
__device__ __forceinline__ void mma_tf32(float* c, const uint32_t* a, const uint32_t* b) {
    asm volatile(
        "mma.sync.aligned.m16n8k8.row.col.f32.tf32.tf32.f32 "
        "{%0,%1,%2,%3},{%4,%5,%6,%7},{%8,%9},{%0,%1,%2,%3};\n"
        : "+f"(c[0]), "+f"(c[1]), "+f"(c[2]), "+f"(c[3])
        : "r"(a[0]), "r"(a[1]), "r"(a[2]), "r"(a[3]), "r"(b[0]), "r"(b[1]));
}
__device__ __forceinline__ void cp16(float* s, const float* g) {
    uint32_t sa = (uint32_t)__cvta_generic_to_shared(s);
    asm volatile("cp.async.cg.shared.global [%0], [%1], 16;" :: "r"(sa), "l"(g));
}

// ---------------- prep kernels ----------------
__global__ void prep_w(const float* __restrict__ Wih, const float* __restrict__ Whh,
                       const float* __restrict__ bih, const float* __restrict__ bhh, int d) {
    int idx = blockIdx.x * blockDim.x + threadIdx.x;
    const int total = 3 * HP * HP;
    if (idx < total) {
        int g = idx / (HP * HP);
        int rem = idx % (HP * HP);
        int j = rem / HP;
        int k = rem % HP;
        float wi = 0.0f, wh = 0.0f;
        if (j < Hh && k < Hh) {
            wi = tf32r(Wih[(size_t)(g * Hh + j) * Hh + k]);
            wh = tf32r(Whh[(size_t)(g * Hh + j) * Hh + k]);
        }
        g_Wi[d][g][j][k] = wi;
        g_Wh[d][g][j][k] = wh;
    }
    if (idx < 3 * HP) {
        int g = idx / HP, j = idx % HP;
        float bi = 0.0f, bh = 0.0f;
        if (j < Hh) { bi = bih[g * Hh + j]; bh = bhh[g * Hh + j]; }
        g_bi[d][g][j] = bi;
        g_bh[d][g][j] = bh;
    }
}

__global__ void prep_x(const float* __restrict__ win) {
    int idx = blockIdx.x * blockDim.x + threadIdx.x;
    const int total = TB * (HP / 4);
    if (idx >= total) return;
    int row = idx / (HP / 4);
    int kq  = idx % (HP / 4);
    int k = kq * 4;
    int t = row / Bb, b = row % Bb;
    float4 v = make_float4(0.f, 0.f, 0.f, 0.f);
    if (k < Hh) {
        v = *(const float4*)(win + (size_t)b * Tt * WIN + (size_t)t * WIN + k);
        v.x = tf32r(v.x); v.y = tf32r(v.y); v.z = tf32r(v.z); v.w = tf32r(v.w);
    }
    *(float4*)&g_X[row][k] = v;
}

__global__ void zero_h() {
    int idx = blockIdx.x * blockDim.x + threadIdx.x;
    const int total = 2 * 2 * Bb * HP;
    if (idx < total) ((float*)g_h)[idx] = 0.0f;
    if (idx == 0) g_bar = 0u;
}

// ---------------- K1: GI = X @ Wih^T + bih ----------------
// grid: (HP/64 = 12, TB/128 = 512, 6), 256 threads
__global__ void k_gi() {
    __shared__ float As[128][36];
    __shared__ float Bs[64][36];

    const int tid  = threadIdx.x;
    const int lane = tid & 31;
    const int w    = tid >> 5;
    const int grp  = lane >> 2;
    const int tg   = lane & 3;
    const int wm   = w >> 1;
    const int wn   = w & 1;

    const int j0   = blockIdx.x * 64;
    const int row0 = blockIdx.y * 128;
    const int dg   = blockIdx.z;
    const int d    = dg / 3, g = dg % 3;

    const float* __restrict__ Ag = &g_X[row0][0];
    const float* __restrict__ Bg = &g_Wi[d][g][j0][0];

    float acc[32];
#pragma unroll
    for (int i = 0; i < 32; i++) acc[i] = 0.0f;

    for (int kt = 0; kt < HP / 32; kt++) {
        const int k0 = kt * 32;
#pragma unroll
        for (int i = 0; i < 4; i++) {
            int li = tid + i * 256;
            int r = li >> 3, kq = li & 7;
            float4 v = *(const float4*)(Ag + (size_t)r * HP + k0 + kq * 4);
            *(float4*)&As[r][kq * 4] = v;
        }
#pragma unroll
        for (int i = 0; i < 2; i++) {
            int li = tid + i * 256;
            int r = li >> 3, kq = li & 7;
            float4 v = *(const float4*)(Bg + (size_t)r * HP + k0 + kq * 4);
            *(float4*)&Bs[r][kq * 4] = v;
        }
        __syncthreads();

#pragma unroll
        for (int kk = 0; kk < 4; kk++) {
            const int kb = kk * 8;
            uint32_t af[2][4];
#pragma unroll
            for (int mi = 0; mi < 2; mi++) {
                int r = wm * 32 + mi * 16 + grp;
                af[mi][0] = __float_as_uint(As[r][kb + tg]);
                af[mi][1] = __float_as_uint(As[r + 8][kb + tg]);
                af[mi][2] = __float_as_uint(As[r][kb + tg + 4]);
                af[mi][3] = __float_as_uint(As[r + 8][kb + tg + 4]);
            }
#pragma unroll
            for (int ni = 0; ni < 4; ni++) {
                int jr = wn * 32 + ni * 8 + grp;
                uint32_t bf[2] = { __float_as_uint(Bs[jr][kb + tg]),
                                   __float_as_uint(Bs[jr][kb + tg + 4]) };
#pragma unroll
                for (int mi = 0; mi < 2; mi++)
                    mma_tf32(&acc[(mi * 4 + ni) * 4], af[mi], bf);
            }
        }
        __syncthreads();
    }

    float* __restrict__ GIp = &g_GI[d][g][0][0];
    const float* __restrict__ bip = &g_bi[d][g][0];
#pragma unroll
    for (int mi = 0; mi < 2; mi++) {
#pragma unroll
        for (int ni = 0; ni < 4; ni++) {
            int r = row0 + wm * 32 + mi * 16 + grp;
            int j = j0 + wn * 32 + ni * 8 + tg * 2;
            float b0 = bip[j], b1 = bip[j + 1];
            float* a = &acc[(mi * 4 + ni) * 4];
            GIp[(size_t)r * HP + j]           = a[0] + b0;
            GIp[(size_t)r * HP + j + 1]       = a[1] + b1;
            GIp[(size_t)(r + 8) * HP + j]     = a[2] + b0;
            GIp[(size_t)(r + 8) * HP + j + 1] = a[3] + b1;
        }
    }
}

// ---------------- persistent recurrent kernel ----------------
// grid: 96 CTAs (dir*48 + jtile), 256 threads (8 warps), smem-resident Whh slice
__device__ __forceinline__ void gbar(unsigned expect) {
    __syncthreads();
    if (threadIdx.x == 0) {
        asm volatile("red.release.gpu.global.add.u32 [%0], 1;" :: "l"(&g_bar) : "memory");
        unsigned v;
        do {
            asm volatile("ld.acquire.gpu.global.u32 %0, [%1];" : "=r"(v) : "l"(&g_bar));
        } while (v < expect);
    }
    __syncthreads();
}

__global__ void __launch_bounds__(256, 1)
k_persist(const float* __restrict__ win, float* __restrict__ out) {
    extern __shared__ float smem[];
    float* Ws  = smem;                       // [48][772]
    float* As0 = smem + NJT * WS_STRIDE * 0 + 48 * WS_STRIDE;  // [256][36]
    float* As1 = As0 + Bb * AS_STRIDE;

    const int tid  = threadIdx.x;
    const int lane = tid & 31;
    const int w    = tid >> 5;
    const int grp  = lane >> 2;
    const int tg   = lane & 3;
    const int m0w  = w * 32;

    const int d  = blockIdx.x / NJT;
    const int j0 = (blockIdx.x % NJT) * JT;

    // load resident weight slice: Ws[c][k], c = g*16+jj  (already tf32-rounded)
    {
        const float* src = &g_Wh[d][0][0][0];   // [3][768][768]
        for (int idx = tid; idx < 48 * (HP / 4); idx += 256) {
            int c = idx / (HP / 4);
            int k4 = (idx % (HP / 4)) * 4;
            int g = c / JT, jj = c % JT;
            float4 v = *(const float4*)(src + ((size_t)g * HP + (j0 + jj)) * HP + k4);
            *(float4*)&Ws[c * WS_STRIDE + k4] = v;
        }
    }
    __syncthreads();

    const size_t PLANE = (size_t)TB * HP;
    const float* __restrict__ GI0 = &g_GI[d][0][0][0];
    const float* __restrict__ bh0 = &g_bh[d][0][0];

    for (int t = 0; t < Tt; t++) {
        const int p  = t & 1;
        const int xt = (d == 0) ? t : (Tt - 1 - t);
        const float* __restrict__ hA = &g_h[p][d][0][0];

        float acc[6][2][4];
#pragma unroll
        for (int nf = 0; nf < 6; nf++)
#pragma unroll
            for (int mi = 0; mi < 2; mi++)
#pragma unroll
                for (int i = 0; i < 4; i++) acc[nf][mi][i] = 0.0f;

        // ---- pipelined GEMM: acc += h[256,768] @ Ws^T ----
        // preload k-tile 0
        {
#pragma unroll
            for (int i = 0; i < 8; i++) {
                int li = tid + i * 256;
                int r = li >> 3, kq = li & 7;
                cp16(&As0[r * AS_STRIDE + kq * 4], hA + (size_t)r * HP + kq * 4);
            }
            asm volatile("cp.async.commit_group;");
        }

        for (int kt = 0; kt < HP / 32; kt++) {
            const int k0 = kt * 32;
            float* Acur = (kt & 1) ? As1 : As0;
            if (kt < HP / 32 - 1) {
                float* Anext = (kt & 1) ? As0 : As1;
                const int kn = k0 + 32;
#pragma unroll
                for (int i = 0; i < 8; i++) {
                    int li = tid + i * 256;
                    int r = li >> 3, kq = li & 7;
                    cp16(&Anext[r * AS_STRIDE + kq * 4], hA + (size_t)r * HP + kn + kq * 4);
                }
                asm volatile("cp.async.commit_group;");
                asm volatile("cp.async.wait_group 1;");
            } else {
                asm volatile("cp.async.wait_group 0;");
            }
            __syncthreads();

#pragma unroll
            for (int kk = 0; kk < 4; kk++) {
                const int kb = kk * 8;
                uint32_t af[2][4];
#pragma unroll
                for (int mi = 0; mi < 2; mi++) {
                    int r = m0w + mi * 16 + grp;
                    af[mi][0] = tf32u(Acur[r * AS_STRIDE + kb + tg]);
                    af[mi][1] = tf32u(Acur[(r + 8) * AS_STRIDE + kb + tg]);
                    af[mi][2] = tf32u(Acur[r * AS_STRIDE + kb + tg + 4]);
                    af[mi][3] = tf32u(Acur[(r + 8) * AS_STRIDE + kb + tg + 4]);
                }
#pragma unroll
                for (int nf = 0; nf < 6; nf++) {
                    int jr = nf * 8 + grp;
                    uint32_t bf[2] = { __float_as_uint(Ws[jr * WS_STRIDE + k0 + kb + tg]),
                                       __float_as_uint(Ws[jr * WS_STRIDE + k0 + kb + tg + 4]) };
                    mma_tf32(acc[nf][0], af[0], bf);
                    mma_tf32(acc[nf][1], af[1], bf);
                }
            }
            __syncthreads();
        }

        // ---- fused GRU epilogue ----
        const bool doOut = (t >= Cc) && (t < Tt - Cc);
        const float* __restrict__ hin = &g_h[p][d][0][0];
        float* __restrict__ hout      = &g_h[p ^ 1][d][0][0];

#pragma unroll
        for (int mi = 0; mi < 2; mi++) {
#pragma unroll
            for (int nf0 = 0; nf0 < 2; nf0++) {
                const int jj = nf0 * 8 + tg * 2;
                const int j  = j0 + jj;
                const float br0 = bh0[j],            br1 = bh0[j + 1];
                const float bz0 = bh0[HP + j],       bz1 = bh0[HP + j + 1];
                const float bn0 = bh0[2 * HP + j],   bn1 = bh0[2 * HP + j + 1];
#pragma unroll
                for (int half = 0; half < 2; half++) {
                    const int b  = m0w + mi * 16 + grp + half * 8;
                    const int ai = half * 2;
                    const float aR0 = acc[nf0][mi][ai],     aR1 = acc[nf0][mi][ai + 1];
                    const float aZ0 = acc[nf0 + 2][mi][ai], aZ1 = acc[nf0 + 2][mi][ai + 1];
                    const float aN0 = acc[nf0 + 4][mi][ai], aN1 = acc[nf0 + 4][mi][ai + 1];

                    const size_t gio = (size_t)(xt * Bb + b) * HP + j;
                    const float gr0 = GI0[gio],              gr1 = GI0[gio + 1];
                    const float gz0 = GI0[PLANE + gio],      gz1 = GI0[PLANE + gio + 1];
                    const float gn0 = GI0[2 * PLANE + gio],  gn1 = GI0[2 * PLANE + gio + 1];

                    const float ho0 = __ldcg(&hin[(size_t)b * HP + j]);
                    const float ho1 = __ldcg(&hin[(size_t)b * HP + j + 1]);

                    const float r0 = sigf(gr0 + aR0 + br0);
                    const float r1 = sigf(gr1 + aR1 + br1);
                    const float z0 = sigf(gz0 + aZ0 + bz0);
                    const float z1 = sigf(gz1 + aZ1 + bz1);
                    const float n0 = tanh_fast(gn0 + r0 * (aN0 + bn0));
                    const float n1 = tanh_fast(gn1 + r1 * (aN1 + bn1));
                    const float h0 = (1.0f - z0) * n0 + z0 * ho0;
                    const float h1 = (1.0f - z1) * n1 + z1 * ho1;

                    hout[(size_t)b * HP + j]     = h0;
                    hout[(size_t)b * HP + j + 1] = h1;

                    if (doOut && j < Hh) {
                        const size_t xo = (size_t)b * Tt * WIN + (size_t)xt * WIN + j;
                        const size_t oo = (size_t)b * (OUTT * OUTW) + (size_t)(t - Cc) * OUTW + d * Hh + j;
                        out[oo]     = h0 + win[xo];
                        out[oo + 1] = h1 + win[xo + 1];
                    }
                }
            }
        }

        gbar((unsigned)NCTA * (unsigned)(t + 1));
    }
}

// ---------------- launch ----------------
extern "C" void kernel_launch(void* const* d_in, const int* in_sizes, int n_in,
                              void* d_out, int out_size) {
    const float* windows = (const float*)d_in[0];
    const float* Wih_f   = (const float*)d_in[1];
    const float* Whh_f   = (const float*)d_in[2];
    const float* bih_f   = (const float*)d_in[3];
    const float* bhh_f   = (const float*)d_in[4];
    const float* Wih_b   = (const float*)d_in[5];
    const float* Whh_b   = (const float*)d_in[6];
    const float* bih_b   = (const float*)d_in[7];
    const float* bhh_b   = (const float*)d_in[8];
    float* out = (float*)d_out;

    const int SMEM_BYTES = (NJT * JT / JT * 48 * 0) + (48 * WS_STRIDE + 2 * Bb * AS_STRIDE) * 4; // 221952
    static int attr_set = 0;
    if (!attr_set) {
        cudaFuncSetAttribute(k_persist, cudaFuncAttributeMaxDynamicSharedMemorySize, SMEM_BYTES);
        attr_set = 1;
    }

    const int wthreads = 256;
    const int wtotal = 3 * HP * HP;
    prep_w<<<(wtotal + wthreads - 1) / wthreads, wthreads>>>(Wih_f, Whh_f, bih_f, bhh_f, 0);
    prep_w<<<(wtotal + wthreads - 1) / wthreads, wthreads>>>(Wih_b, Whh_b, bih_b, bhh_b, 1);

    const int xtotal = TB * (HP / 4);
    prep_x<<<(xtotal + 255) / 256, 256>>>(windows);

    const int htotal = 2 * 2 * Bb * HP;
    zero_h<<<(htotal + 255) / 256, 256>>>();

    k_gi<<<dim3(HP / 64, TB / 128, 6), 256>>>();

    k_persist<<<NCTA, 256, SMEM_BYTES>>>(windows, out);
}

// round 4
// speedup vs baseline: 1.5787x; 1.3935x over previous
#include <cuda_runtime.h>
#include <cuda_fp16.h>
#include <cstdint>

#define Hh   744
#define HP   768
#define Bb   256
#define Tt   256
#define Cc   16
#define WIN  800
#define TB   (Tt*Bb)          // 65536
#define OUTT (Tt - 2*Cc)      // 224
#define OUTW (2*Hh)           // 1488

#define NJT    48
#define JT     16
#define NCTA   (2*NJT)
#define WS_STRIDE 776         // halfs: 768 + 8 pad (conflict-free)
#define AS_STRIDE 40          // halfs: 32 + 8 pad

// ---------------- scratch ----------------
__device__ __half g_Wi16[2][3][HP][HP];
__device__ __half g_Wh16[2][3][HP][HP];
__device__ float  g_bi[2][3][HP];
__device__ float  g_bh[2][3][HP];
__device__ __half g_X16[TB][HP];
__device__ float  g_GI[2][3][TB][HP];
__device__ float  g_h  [2][2][Bb][HP];   // fp32 carried state
__device__ __half g_h16[2][2][Bb][HP];   // fp16 mirror for MMA A-operand
__device__ unsigned g_bar;

// ---------------- helpers ----------------
__device__ __forceinline__ float sigf(float x) { return 1.0f / (1.0f + __expf(-x)); }
__device__ __forceinline__ float tanh_fast(float x) {
    x = fminf(15.0f, fmaxf(-15.0f, x));
    float e = __expf(2.0f * x);
    return (e - 1.0f) / (e + 1.0f);
}
// m16n8k16 fp16 inputs, fp32 accumulate
__device__ __forceinline__ void mma_fp16(float* c, const uint32_t* a, const uint32_t* b) {
    asm volatile(
        "mma.sync.aligned.m16n8k16.row.col.f32.f16.f16.f32 "
        "{%0,%1,%2,%3},{%4,%5,%6,%7},{%8,%9},{%0,%1,%2,%3};\n"
        : "+f"(c[0]), "+f"(c[1]), "+f"(c[2]), "+f"(c[3])
        : "r"(a[0]), "r"(a[1]), "r"(a[2]), "r"(a[3]), "r"(b[0]), "r"(b[1]));
}
__device__ __forceinline__ void cp16h(__half* s, const __half* g) {
    uint32_t sa = (uint32_t)__cvta_generic_to_shared(s);
    asm volatile("cp.async.cg.shared.global [%0], [%1], 16;" :: "r"(sa), "l"(g));
}
__device__ __forceinline__ uint32_t ldu32s(const __half* p) {
    return *(const uint32_t*)p;
}

// ---------------- prep kernels ----------------
__global__ void prep_w(const float* __restrict__ Wih, const float* __restrict__ Whh,
                       const float* __restrict__ bih, const float* __restrict__ bhh, int d) {
    int idx = blockIdx.x * blockDim.x + threadIdx.x;
    const int total = 3 * HP * HP;
    if (idx < total) {
        int g = idx / (HP * HP);
        int rem = idx % (HP * HP);
        int j = rem / HP;
        int k = rem % HP;
        float wi = 0.0f, wh = 0.0f;
        if (j < Hh && k < Hh) {
            wi = Wih[(size_t)(g * Hh + j) * Hh + k];
            wh = Whh[(size_t)(g * Hh + j) * Hh + k];
        }
        g_Wi16[d][g][j][k] = __float2half_rn(wi);
        g_Wh16[d][g][j][k] = __float2half_rn(wh);
    }
    if (idx < 3 * HP) {
        int g = idx / HP, j = idx % HP;
        float bi = 0.0f, bh = 0.0f;
        if (j < Hh) { bi = bih[g * Hh + j]; bh = bhh[g * Hh + j]; }
        g_bi[d][g][j] = bi;
        g_bh[d][g][j] = bh;
    }
}

__global__ void prep_x(const float* __restrict__ win) {
    int idx = blockIdx.x * blockDim.x + threadIdx.x;
    const int total = TB * (HP / 4);
    if (idx >= total) return;
    int row = idx / (HP / 4);
    int kq  = idx % (HP / 4);
    int k = kq * 4;
    int t = row / Bb, b = row % Bb;
    float4 v = make_float4(0.f, 0.f, 0.f, 0.f);
    if (k < Hh) {
        v = *(const float4*)(win + (size_t)b * Tt * WIN + (size_t)t * WIN + k);
    }
    __half2* dst = (__half2*)&g_X16[row][k];
    dst[0] = __floats2half2_rn(v.x, v.y);
    dst[1] = __floats2half2_rn(v.z, v.w);
}

__global__ void zero_h() {
    int idx = blockIdx.x * blockDim.x + threadIdx.x;
    const int total = 2 * 2 * Bb * HP;               // 786432
    if (idx < total) ((float*)g_h)[idx] = 0.0f;
    if (idx < total / 2) ((uint32_t*)g_h16)[idx] = 0u;   // 786432 halfs = 393216 u32
    if (idx == 0) g_bar = 0u;
}

// ---------------- K1: GI = X @ Wih^T + bih (fp16 MMA) ----------------
// grid: (12, 512, 6), 256 threads; per CTA 128(M) x 64(N), K chunks of 32
__global__ void __launch_bounds__(256) k_gi() {
    __shared__ __half As[128][AS_STRIDE];
    __shared__ __half Bs[64][AS_STRIDE];

    const int tid  = threadIdx.x;
    const int lane = tid & 31;
    const int w    = tid >> 5;
    const int grp  = lane >> 2;
    const int tg   = lane & 3;
    const int wm   = w >> 1;
    const int wn   = w & 1;

    const int j0   = blockIdx.x * 64;
    const int row0 = blockIdx.y * 128;
    const int dg   = blockIdx.z;
    const int d    = dg / 3, g = dg % 3;

    const __half* __restrict__ Ag = &g_X16[row0][0];
    const __half* __restrict__ Bg = &g_Wi16[d][g][j0][0];

    float acc[32];
#pragma unroll
    for (int i = 0; i < 32; i++) acc[i] = 0.0f;

    for (int kt = 0; kt < HP / 32; kt++) {
        const int k0 = kt * 32;
#pragma unroll
        for (int i = 0; i < 2; i++) {            // A: 128 rows x 32 halfs = 512 x 16B
            int li = tid + i * 256;
            int r = li >> 2, kq = li & 3;
            *(uint4*)&As[r][kq * 8] = *(const uint4*)(Ag + (size_t)r * HP + k0 + kq * 8);
        }
        {                                        // B: 64 rows x 32 halfs = 256 x 16B
            int r = tid >> 2, kq = tid & 3;
            *(uint4*)&Bs[r][kq * 8] = *(const uint4*)(Bg + (size_t)r * HP + k0 + kq * 8);
        }
        __syncthreads();

#pragma unroll
        for (int kk = 0; kk < 2; kk++) {
            const int kb = kk * 16;
            uint32_t af[2][4];
#pragma unroll
            for (int mi = 0; mi < 2; mi++) {
                int r = wm * 32 + mi * 16 + grp;
                af[mi][0] = ldu32s(&As[r][kb + tg * 2]);
                af[mi][1] = ldu32s(&As[r + 8][kb + tg * 2]);
                af[mi][2] = ldu32s(&As[r][kb + 8 + tg * 2]);
                af[mi][3] = ldu32s(&As[r + 8][kb + 8 + tg * 2]);
            }
#pragma unroll
            for (int ni = 0; ni < 4; ni++) {
                int jr = wn * 32 + ni * 8 + grp;
                uint32_t bf[2] = { ldu32s(&Bs[jr][kb + tg * 2]),
                                   ldu32s(&Bs[jr][kb + 8 + tg * 2]) };
#pragma unroll
                for (int mi = 0; mi < 2; mi++)
                    mma_fp16(&acc[(mi * 4 + ni) * 4], af[mi], bf);
            }
        }
        __syncthreads();
    }

    float* __restrict__ GIp = &g_GI[d][g][0][0];
    const float* __restrict__ bip = &g_bi[d][g][0];
#pragma unroll
    for (int mi = 0; mi < 2; mi++) {
#pragma unroll
        for (int ni = 0; ni < 4; ni++) {
            int r = row0 + wm * 32 + mi * 16 + grp;
            int j = j0 + wn * 32 + ni * 8 + tg * 2;
            float b0 = bip[j], b1 = bip[j + 1];
            float* a = &acc[(mi * 4 + ni) * 4];
            GIp[(size_t)r * HP + j]           = a[0] + b0;
            GIp[(size_t)r * HP + j + 1]       = a[1] + b1;
            GIp[(size_t)(r + 8) * HP + j]     = a[2] + b0;
            GIp[(size_t)(r + 8) * HP + j + 1] = a[3] + b1;
        }
    }
}

// ---------------- persistent recurrent kernel (fp16 MMA) ----------------
__device__ __forceinline__ void gbar(unsigned expect) {
    __syncthreads();
    if (threadIdx.x == 0) {
        asm volatile("red.release.gpu.global.add.u32 [%0], 1;" :: "l"(&g_bar) : "memory");
        unsigned v;
        do {
            asm volatile("ld.acquire.gpu.global.u32 %0, [%1];" : "=r"(v) : "l"(&g_bar));
        } while (v < expect);
    }
    __syncthreads();
}

__global__ void __launch_bounds__(256, 1)
k_persist(const float* __restrict__ win, float* __restrict__ out) {
    extern __shared__ __half smemh[];
    __half* Ws  = smemh;                          // [48][776]
    __half* As0 = smemh + 48 * WS_STRIDE;         // [256][40]
    __half* As1 = As0 + Bb * AS_STRIDE;

    const int tid  = threadIdx.x;
    const int lane = tid & 31;
    const int w    = tid >> 5;
    const int grp  = lane >> 2;
    const int tg   = lane & 3;
    const int m0w  = w * 32;

    const int d  = blockIdx.x / NJT;
    const int j0 = (blockIdx.x % NJT) * JT;

    // resident weight slice: Ws[c][k], c = g*16+jj
    {
        const __half* src = &g_Wh16[d][0][0][0];
        for (int idx = tid; idx < 48 * (HP / 8); idx += 256) {
            int c = idx / (HP / 8);
            int k8 = (idx % (HP / 8)) * 8;
            int g = c / JT, jj = c % JT;
            *(uint4*)&Ws[c * WS_STRIDE + k8] =
                *(const uint4*)(src + ((size_t)g * HP + (j0 + jj)) * HP + k8);
        }
    }
    __syncthreads();

    const size_t PLANE = (size_t)TB * HP;
    const float* __restrict__ GI0 = &g_GI[d][0][0][0];
    const float* __restrict__ bh0 = &g_bh[d][0][0];

    for (int t = 0; t < Tt; t++) {
        const int p  = t & 1;
        const int xt = (d == 0) ? t : (Tt - 1 - t);
        const __half* __restrict__ hA = &g_h16[p][d][0][0];

        float acc[6][2][4];
#pragma unroll
        for (int nf = 0; nf < 6; nf++)
#pragma unroll
            for (int mi = 0; mi < 2; mi++)
#pragma unroll
                for (int i = 0; i < 4; i++) acc[nf][mi][i] = 0.0f;

        // preload k-tile 0: 256 rows x 32 halfs = 1024 x 16B chunks / 256 thr
        {
#pragma unroll
            for (int i = 0; i < 4; i++) {
                int li = tid + i * 256;
                int r = li >> 2, kq = li & 3;
                cp16h(&As0[r * AS_STRIDE + kq * 8], hA + (size_t)r * HP + kq * 8);
            }
            asm volatile("cp.async.commit_group;");
        }

        for (int kt = 0; kt < HP / 32; kt++) {
            const int k0 = kt * 32;
            __half* Acur = (kt & 1) ? As1 : As0;
            if (kt < HP / 32 - 1) {
                __half* Anext = (kt & 1) ? As0 : As1;
                const int kn = k0 + 32;
#pragma unroll
                for (int i = 0; i < 4; i++) {
                    int li = tid + i * 256;
                    int r = li >> 2, kq = li & 3;
                    cp16h(&Anext[r * AS_STRIDE + kq * 8], hA + (size_t)r * HP + kn + kq * 8);
                }
                asm volatile("cp.async.commit_group;");
                asm volatile("cp.async.wait_group 1;");
            } else {
                asm volatile("cp.async.wait_group 0;");
            }
            __syncthreads();

#pragma unroll
            for (int kk = 0; kk < 2; kk++) {
                const int kb = kk * 16;
                uint32_t af[2][4];
#pragma unroll
                for (int mi = 0; mi < 2; mi++) {
                    int r = m0w + mi * 16 + grp;
                    af[mi][0] = ldu32s(&Acur[r * AS_STRIDE + kb + tg * 2]);
                    af[mi][1] = ldu32s(&Acur[(r + 8) * AS_STRIDE + kb + tg * 2]);
                    af[mi][2] = ldu32s(&Acur[r * AS_STRIDE + kb + 8 + tg * 2]);
                    af[mi][3] = ldu32s(&Acur[(r + 8) * AS_STRIDE + kb + 8 + tg * 2]);
                }
#pragma unroll
                for (int nf = 0; nf < 6; nf++) {
                    int jr = nf * 8 + grp;
                    uint32_t bf[2] = { ldu32s(&Ws[jr * WS_STRIDE + k0 + kb + tg * 2]),
                                       ldu32s(&Ws[jr * WS_STRIDE + k0 + kb + 8 + tg * 2]) };
                    mma_fp16(acc[nf][0], af[0], bf);
                    mma_fp16(acc[nf][1], af[1], bf);
                }
            }
            __syncthreads();
        }

        // ---- fused GRU epilogue ----
        const bool doOut = (t >= Cc) && (t < Tt - Cc);
        const float*  __restrict__ hin    = &g_h[p][d][0][0];
        float*  __restrict__ hout         = &g_h[p ^ 1][d][0][0];
        __half* __restrict__ hout16       = &g_h16[p ^ 1][d][0][0];

#pragma unroll
        for (int mi = 0; mi < 2; mi++) {
#pragma unroll
            for (int nf0 = 0; nf0 < 2; nf0++) {
                const int jj = nf0 * 8 + tg * 2;
                const int j  = j0 + jj;
                const float br0 = bh0[j],            br1 = bh0[j + 1];
                const float bz0 = bh0[HP + j],       bz1 = bh0[HP + j + 1];
                const float bn0 = bh0[2 * HP + j],   bn1 = bh0[2 * HP + j + 1];
#pragma unroll
                for (int half2i = 0; half2i < 2; half2i++) {
                    const int b  = m0w + mi * 16 + grp + half2i * 8;
                    const int ai = half2i * 2;
                    const float aR0 = acc[nf0][mi][ai],     aR1 = acc[nf0][mi][ai + 1];
                    const float aZ0 = acc[nf0 + 2][mi][ai], aZ1 = acc[nf0 + 2][mi][ai + 1];
                    const float aN0 = acc[nf0 + 4][mi][ai], aN1 = acc[nf0 + 4][mi][ai + 1];

                    const size_t gio = (size_t)(xt * Bb + b) * HP + j;
                    const float gr0 = GI0[gio],              gr1 = GI0[gio + 1];
                    const float gz0 = GI0[PLANE + gio],      gz1 = GI0[PLANE + gio + 1];
                    const float gn0 = GI0[2 * PLANE + gio],  gn1 = GI0[2 * PLANE + gio + 1];

                    const float ho0 = __ldcg(&hin[(size_t)b * HP + j]);
                    const float ho1 = __ldcg(&hin[(size_t)b * HP + j + 1]);

                    const float r0 = sigf(gr0 + aR0 + br0);
                    const float r1 = sigf(gr1 + aR1 + br1);
                    const float z0 = sigf(gz0 + aZ0 + bz0);
                    const float z1 = sigf(gz1 + aZ1 + bz1);
                    const float n0 = tanh_fast(gn0 + r0 * (aN0 + bn0));
                    const float n1 = tanh_fast(gn1 + r1 * (aN1 + bn1));
                    const float h0 = (1.0f - z0) * n0 + z0 * ho0;
                    const float h1 = (1.0f - z1) * n1 + z1 * ho1;

                    hout[(size_t)b * HP + j]     = h0;
                    hout[(size_t)b * HP + j + 1] = h1;
                    *(__half2*)&hout16[(size_t)b * HP + j] = __floats2half2_rn(h0, h1);

                    if (doOut && j < Hh) {
                        const size_t xo = (size_t)b * Tt * WIN + (size_t)xt * WIN + j;
                        const size_t oo = (size_t)b * (OUTT * OUTW) + (size_t)(t - Cc) * OUTW + d * Hh + j;
                        out[oo]     = h0 + win[xo];
                        out[oo + 1] = h1 + win[xo + 1];
                    }
                }
            }
        }

        gbar((unsigned)NCTA * (unsigned)(t + 1));
    }
}

// ---------------- launch ----------------
extern "C" void kernel_launch(void* const* d_in, const int* in_sizes, int n_in,
                              void* d_out, int out_size) {
    const float* windows = (const float*)d_in[0];
    const float* Wih_f   = (const float*)d_in[1];
    const float* Whh_f   = (const float*)d_in[2];
    const float* bih_f   = (const float*)d_in[3];
    const float* bhh_f   = (const float*)d_in[4];
    const float* Wih_b   = (const float*)d_in[5];
    const float* Whh_b   = (const float*)d_in[6];
    const float* bih_b   = (const float*)d_in[7];
    const float* bhh_b   = (const float*)d_in[8];
    float* out = (float*)d_out;

    const int PERSIST_SMEM = (48 * WS_STRIDE + 2 * Bb * AS_STRIDE) * 2;  // bytes (half)
    static int attr_set = 0;
    if (!attr_set) {
        cudaFuncSetAttribute(k_persist, cudaFuncAttributeMaxDynamicSharedMemorySize, PERSIST_SMEM);
        attr_set = 1;
    }

    const int wthreads = 256;
    const int wtotal = 3 * HP * HP;
    prep_w<<<(wtotal + wthreads - 1) / wthreads, wthreads>>>(Wih_f, Whh_f, bih_f, bhh_f, 0);
    prep_w<<<(wtotal + wthreads - 1) / wthreads, wthreads>>>(Wih_b, Whh_b, bih_b, bhh_b, 1);

    const int xtotal = TB * (HP / 4);
    prep_x<<<(xtotal + 255) / 256, 256>>>(windows);

    const int htotal = 2 * 2 * Bb * HP;
    zero_h<<<(htotal + 255) / 256, 256>>>();

    k_gi<<<dim3(HP / 64, TB / 128, 6), 256>>>();

    k_persist<<<NCTA, 256, PERSIST_SMEM>>>(windows, out);
}

// round 5
// speedup vs baseline: 1.9168x; 1.2141x over previous
#include <cuda_runtime.h>
#include <cuda_fp16.h>
#include <cstdint>

#define Hh   744
#define HP   768
#define Bb   256
#define Tt   256
#define Cc   16
#define WIN  800
#define TB   (Tt*Bb)          // 65536
#define OUTT (Tt - 2*Cc)      // 224
#define OUTW (2*Hh)           // 1488

#define NJT    48
#define JT     16
#define NCTA   (2*NJT)
#define WS_STRIDE 776         // halfs: 768 + 8 pad
#define AS_STRIDE 40          // halfs: 32 + 8 pad
#define GI_AST    40          // halfs

// ---------------- scratch ----------------
__device__ __half g_Wi16[2][3][HP][HP];
__device__ __half g_Wh16[2][3][HP][HP];
__device__ float  g_bi[2][3][HP];
__device__ float  g_bh[2][3][HP];
__device__ __half g_X16[TB][HP];
__device__ float  g_GI[2][3][TB][HP];
__device__ float  g_h  [2][2][Bb][HP];   // fp32 carried state
__device__ __half g_h16[2][2][Bb][HP];   // fp16 mirror (MMA A-operand)
__device__ unsigned g_bar;

// ---------------- helpers ----------------
__device__ __forceinline__ float sigf(float x) { return 1.0f / (1.0f + __expf(-x)); }
__device__ __forceinline__ float tanh_fast(float x) {
    x = fminf(15.0f, fmaxf(-15.0f, x));
    float e = __expf(2.0f * x);
    return (e - 1.0f) / (e + 1.0f);
}
__device__ __forceinline__ void mma_fp16(float* c, const uint32_t* a, const uint32_t* b) {
    asm volatile(
        "mma.sync.aligned.m16n8k16.row.col.f32.f16.f16.f32 "
        "{%0,%1,%2,%3},{%4,%5,%6,%7},{%8,%9},{%0,%1,%2,%3};\n"
        : "+f"(c[0]), "+f"(c[1]), "+f"(c[2]), "+f"(c[3])
        : "r"(a[0]), "r"(a[1]), "r"(a[2]), "r"(a[3]), "r"(b[0]), "r"(b[1]));
}
__device__ __forceinline__ void cp16h(__half* s, const __half* g) {
    uint32_t sa = (uint32_t)__cvta_generic_to_shared(s);
    asm volatile("cp.async.cg.shared.global [%0], [%1], 16;" :: "r"(sa), "l"(g));
}
__device__ __forceinline__ uint32_t s2u(const void* p) {
    return (uint32_t)__cvta_generic_to_shared(p);
}
__device__ __forceinline__ void ldsm4(uint32_t* r, uint32_t addr) {
    asm volatile("ldmatrix.sync.aligned.m8n8.x4.shared.b16 {%0,%1,%2,%3}, [%4];"
        : "=r"(r[0]), "=r"(r[1]), "=r"(r[2]), "=r"(r[3]) : "r"(addr));
}

// ---------------- prep kernels ----------------
__global__ void prep_w(const float* __restrict__ Wih, const float* __restrict__ Whh,
                       const float* __restrict__ bih, const float* __restrict__ bhh, int d) {
    int idx = blockIdx.x * blockDim.x + threadIdx.x;
    const int total = 3 * HP * HP;
    if (idx < total) {
        int g = idx / (HP * HP);
        int rem = idx % (HP * HP);
        int j = rem / HP;
        int k = rem % HP;
        float wi = 0.0f, wh = 0.0f;
        if (j < Hh && k < Hh) {
            wi = Wih[(size_t)(g * Hh + j) * Hh + k];
            wh = Whh[(size_t)(g * Hh + j) * Hh + k];
        }
        g_Wi16[d][g][j][k] = __float2half_rn(wi);
        g_Wh16[d][g][j][k] = __float2half_rn(wh);
    }
    if (idx < 3 * HP) {
        int g = idx / HP, j = idx % HP;
        float bi = 0.0f, bh = 0.0f;
        if (j < Hh) { bi = bih[g * Hh + j]; bh = bhh[g * Hh + j]; }
        g_bi[d][g][j] = bi;
        g_bh[d][g][j] = bh;
    }
}

__global__ void prep_x(const float* __restrict__ win) {
    int idx = blockIdx.x * blockDim.x + threadIdx.x;
    const int total = TB * (HP / 4);
    if (idx >= total) return;
    int row = idx / (HP / 4);
    int kq  = idx % (HP / 4);
    int k = kq * 4;
    int t = row / Bb, b = row % Bb;
    float4 v = make_float4(0.f, 0.f, 0.f, 0.f);
    if (k < Hh) {
        v = *(const float4*)(win + (size_t)b * Tt * WIN + (size_t)t * WIN + k);
    }
    __half2* dst = (__half2*)&g_X16[row][k];
    dst[0] = __floats2half2_rn(v.x, v.y);
    dst[1] = __floats2half2_rn(v.z, v.w);
}

__global__ void zero_h() {
    int idx = blockIdx.x * blockDim.x + threadIdx.x;
    const int total = 2 * 2 * Bb * HP;
    if (idx < total) ((float*)g_h)[idx] = 0.0f;
    if (idx < total / 2) ((uint32_t*)g_h16)[idx] = 0u;
    if (idx == 0) g_bar = 0u;
}

// ---------------- K1: GI = X @ Wih^T + bih ----------------
// grid (6, 512, 6): per CTA 128(M) x 128(N); 8 warps as 4(m) x 2(n); double-buffered cp.async
__global__ void __launch_bounds__(256, 2) k_gi() {
    __shared__ __half As[2][128][GI_AST];
    __shared__ __half Bs[2][128][GI_AST];

    const int tid  = threadIdx.x;
    const int lane = tid & 31;
    const int w    = tid >> 5;
    const int grp  = lane >> 2;
    const int tg   = lane & 3;
    const int wm   = w >> 1;   // 0..3 -> m offset *32
    const int wn   = w & 1;    // 0..1 -> n offset *64

    const int j0   = blockIdx.x * 128;
    const int row0 = blockIdx.y * 128;
    const int dg   = blockIdx.z;
    const int d    = dg / 3, g = dg % 3;

    const __half* __restrict__ Ag = &g_X16[row0][0];
    const __half* __restrict__ Bg = &g_Wi16[d][g][j0][0];

    // LDSM lane offsets
    const int a_row  = lane & 15;
    const int a_koff = (lane >> 4) * 8;
    const int b_row  = ((lane >> 4)) * 8 + (lane & 7);
    const int b_koff = ((lane >> 3) & 1) * 8;

    float acc[8][2][4];
#pragma unroll
    for (int nf = 0; nf < 8; nf++)
#pragma unroll
        for (int mi = 0; mi < 2; mi++)
#pragma unroll
            for (int i = 0; i < 4; i++) acc[nf][mi][i] = 0.0f;

    const uint32_t as_u[2] = { s2u(&As[0][0][0]), s2u(&As[1][0][0]) };
    const uint32_t bs_u[2] = { s2u(&Bs[0][0][0]), s2u(&Bs[1][0][0]) };
    const uint32_t a_off = ((wm * 32 + a_row) * GI_AST + a_koff) * 2;
    const uint32_t b_off = ((wn * 64 + b_row) * GI_AST + b_koff) * 2;

    auto loadstage = [&](int kt, int s) {
        const int k0 = kt * 32;
#pragma unroll
        for (int i = 0; i < 2; i++) {
            int li = tid + i * 256;
            int r = li >> 2, kq = li & 3;
            cp16h(&As[s][r][kq * 8], Ag + (size_t)r * HP + k0 + kq * 8);
        }
#pragma unroll
        for (int i = 0; i < 2; i++) {
            int li = tid + i * 256;
            int r = li >> 2, kq = li & 3;
            cp16h(&Bs[s][r][kq * 8], Bg + (size_t)r * HP + k0 + kq * 8);
        }
        asm volatile("cp.async.commit_group;");
    };

    loadstage(0, 0);

    for (int kt = 0; kt < HP / 32; kt++) {
        const int s = kt & 1;
        if (kt < HP / 32 - 1) {
            loadstage(kt + 1, s ^ 1);
            asm volatile("cp.async.wait_group 1;");
        } else {
            asm volatile("cp.async.wait_group 0;");
        }
        __syncthreads();

        const uint32_t ab = as_u[s] + a_off;
        const uint32_t bb = bs_u[s] + b_off;
#pragma unroll
        for (int kk = 0; kk < 2; kk++) {
            uint32_t af[2][4];
            ldsm4(af[0], ab + kk * 32);
            ldsm4(af[1], ab + 16 * GI_AST * 2 + kk * 32);
#pragma unroll
            for (int p = 0; p < 4; p++) {
                uint32_t bf[4];
                ldsm4(bf, bb + p * 16 * GI_AST * 2 + kk * 32);
                mma_fp16(acc[2 * p][0],     af[0], bf);
                mma_fp16(acc[2 * p][1],     af[1], bf);
                mma_fp16(acc[2 * p + 1][0], af[0], bf + 2);
                mma_fp16(acc[2 * p + 1][1], af[1], bf + 2);
            }
        }
        __syncthreads();
    }

    float* __restrict__ GIp = &g_GI[d][g][0][0];
    const float* __restrict__ bip = &g_bi[d][g][0];
#pragma unroll
    for (int mi = 0; mi < 2; mi++) {
#pragma unroll
        for (int nf = 0; nf < 8; nf++) {
            int r = row0 + wm * 32 + mi * 16 + grp;
            int j = j0 + wn * 64 + nf * 8 + tg * 2;
            float b0 = bip[j], b1 = bip[j + 1];
            float* a = acc[nf][mi];
            GIp[(size_t)r * HP + j]           = a[0] + b0;
            GIp[(size_t)r * HP + j + 1]       = a[1] + b1;
            GIp[(size_t)(r + 8) * HP + j]     = a[2] + b0;
            GIp[(size_t)(r + 8) * HP + j + 1] = a[3] + b1;
        }
    }
}

// ---------------- persistent recurrent kernel ----------------
__device__ __forceinline__ void gbar(unsigned expect) {
    __syncthreads();
    if (threadIdx.x == 0) {
        asm volatile("red.release.gpu.global.add.u32 [%0], 1;" :: "l"(&g_bar) : "memory");
        unsigned v;
        do {
            asm volatile("ld.acquire.gpu.global.u32 %0, [%1];" : "=r"(v) : "l"(&g_bar));
        } while (v < expect);
    }
    __syncthreads();
}

__global__ void __launch_bounds__(256, 1)
k_persist(const float* __restrict__ win, float* __restrict__ out) {
    extern __shared__ __half smemh[];
    __half* Ws  = smemh;                          // [48][776]
    __half* As0 = smemh + 48 * WS_STRIDE;         // [256][40]
    __half* As1 = As0 + Bb * AS_STRIDE;

    const int tid  = threadIdx.x;
    const int lane = tid & 31;
    const int w    = tid >> 5;
    const int grp  = lane >> 2;
    const int tg   = lane & 3;
    const int m0w  = w * 32;

    const int d  = blockIdx.x / NJT;
    const int j0 = (blockIdx.x % NJT) * JT;

    // resident weight slice: Ws[c][k], c = g*16+jj
    {
        const __half* src = &g_Wh16[d][0][0][0];
        for (int idx = tid; idx < 48 * (HP / 8); idx += 256) {
            int c = idx / (HP / 8);
            int k8 = (idx % (HP / 8)) * 8;
            int g = c / JT, jj = c % JT;
            *(uint4*)&Ws[c * WS_STRIDE + k8] =
                *(const uint4*)(src + ((size_t)g * HP + (j0 + jj)) * HP + k8);
        }
    }
    __syncthreads();

    // LDSM lane offsets
    const int a_row  = lane & 15;
    const int a_koff = (lane >> 4) * 8;
    const int b_row  = ((lane >> 4)) * 8 + (lane & 7);
    const int b_koff = ((lane >> 3) & 1) * 8;

    const uint32_t asu[2] = { s2u(As0), s2u(As1) };
    const uint32_t a_off = ((m0w + a_row) * AS_STRIDE + a_koff) * 2;
    uint32_t wsp[3];
#pragma unroll
    for (int p = 0; p < 3; p++)
        wsp[p] = s2u(Ws) + ((p * 16 + b_row) * WS_STRIDE + b_koff) * 2;

    const size_t PLANE = (size_t)TB * HP;
    const float* __restrict__ GI0 = &g_GI[d][0][0][0];
    const float* __restrict__ bh0 = &g_bh[d][0][0];

    for (int t = 0; t < Tt; t++) {
        const int p  = t & 1;
        const int xt = (d == 0) ? t : (Tt - 1 - t);
        const __half* __restrict__ hA = &g_h16[p][d][0][0];

        float acc[6][2][4];
#pragma unroll
        for (int nf = 0; nf < 6; nf++)
#pragma unroll
            for (int mi = 0; mi < 2; mi++)
#pragma unroll
                for (int i = 0; i < 4; i++) acc[nf][mi][i] = 0.0f;

        {
#pragma unroll
            for (int i = 0; i < 4; i++) {
                int li = tid + i * 256;
                int r = li >> 2, kq = li & 3;
                cp16h(&As0[r * AS_STRIDE + kq * 8], hA + (size_t)r * HP + kq * 8);
            }
            asm volatile("cp.async.commit_group;");
        }

        for (int kt = 0; kt < HP / 32; kt++) {
            const int k0 = kt * 32;
            const int s = kt & 1;
            if (kt < HP / 32 - 1) {
                __half* Anext = s ? As0 : As1;
                const int kn = k0 + 32;
#pragma unroll
                for (int i = 0; i < 4; i++) {
                    int li = tid + i * 256;
                    int r = li >> 2, kq = li & 3;
                    cp16h(&Anext[r * AS_STRIDE + kq * 8], hA + (size_t)r * HP + kn + kq * 8);
                }
                asm volatile("cp.async.commit_group;");
                asm volatile("cp.async.wait_group 1;");
            } else {
                asm volatile("cp.async.wait_group 0;");
            }
            __syncthreads();

            const uint32_t ab = asu[s] + a_off;
#pragma unroll
            for (int kk = 0; kk < 2; kk++) {
                uint32_t af[2][4];
                ldsm4(af[0], ab + kk * 32);
                ldsm4(af[1], ab + 16 * AS_STRIDE * 2 + kk * 32);
#pragma unroll
                for (int pg = 0; pg < 3; pg++) {
                    uint32_t bf[4];
                    ldsm4(bf, wsp[pg] + (k0 + kk * 16) * 2);
                    mma_fp16(acc[2 * pg][0],     af[0], bf);
                    mma_fp16(acc[2 * pg][1],     af[1], bf);
                    mma_fp16(acc[2 * pg + 1][0], af[0], bf + 2);
                    mma_fp16(acc[2 * pg + 1][1], af[1], bf + 2);
                }
            }
            __syncthreads();
        }

        // ---- fused GRU epilogue ----
        const bool doOut = (t >= Cc) && (t < Tt - Cc);
        const float*  __restrict__ hin    = &g_h[p][d][0][0];
        float*  __restrict__ hout         = &g_h[p ^ 1][d][0][0];
        __half* __restrict__ hout16       = &g_h16[p ^ 1][d][0][0];

#pragma unroll
        for (int mi = 0; mi < 2; mi++) {
#pragma unroll
            for (int nf0 = 0; nf0 < 2; nf0++) {
                const int jj = nf0 * 8 + tg * 2;
                const int j  = j0 + jj;
                const float br0 = bh0[j],            br1 = bh0[j + 1];
                const float bz0 = bh0[HP + j],       bz1 = bh0[HP + j + 1];
                const float bn0 = bh0[2 * HP + j],   bn1 = bh0[2 * HP + j + 1];
#pragma unroll
                for (int half2i = 0; half2i < 2; half2i++) {
                    const int b  = m0w + mi * 16 + grp + half2i * 8;
                    const int ai = half2i * 2;
                    const float aR0 = acc[nf0][mi][ai],     aR1 = acc[nf0][mi][ai + 1];
                    const float aZ0 = acc[nf0 + 2][mi][ai], aZ1 = acc[nf0 + 2][mi][ai + 1];
                    const float aN0 = acc[nf0 + 4][mi][ai], aN1 = acc[nf0 + 4][mi][ai + 1];

                    const size_t gio = (size_t)(xt * Bb + b) * HP + j;
                    const float gr0 = GI0[gio],              gr1 = GI0[gio + 1];
                    const float gz0 = GI0[PLANE + gio],      gz1 = GI0[PLANE + gio + 1];
                    const float gn0 = GI0[2 * PLANE + gio],  gn1 = GI0[2 * PLANE + gio + 1];

                    const float ho0 = __ldcg(&hin[(size_t)b * HP + j]);
                    const float ho1 = __ldcg(&hin[(size_t)b * HP + j + 1]);

                    const float r0 = sigf(gr0 + aR0 + br0);
                    const float r1 = sigf(gr1 + aR1 + br1);
                    const float z0 = sigf(gz0 + aZ0 + bz0);
                    const float z1 = sigf(gz1 + aZ1 + bz1);
                    const float n0 = tanh_fast(gn0 + r0 * (aN0 + bn0));
                    const float n1 = tanh_fast(gn1 + r1 * (aN1 + bn1));
                    const float h0 = (1.0f - z0) * n0 + z0 * ho0;
                    const float h1 = (1.0f - z1) * n1 + z1 * ho1;

                    hout[(size_t)b * HP + j]     = h0;
                    hout[(size_t)b * HP + j + 1] = h1;
                    *(__half2*)&hout16[(size_t)b * HP + j] = __floats2half2_rn(h0, h1);

                    if (doOut && j < Hh) {
                        const size_t xo = (size_t)b * Tt * WIN + (size_t)xt * WIN + j;
                        const size_t oo = (size_t)b * (OUTT * OUTW) + (size_t)(t - Cc) * OUTW + d * Hh + j;
                        out[oo]     = h0 + win[xo];
                        out[oo + 1] = h1 + win[xo + 1];
                    }
                }
            }
        }

        gbar((unsigned)NCTA * (unsigned)(t + 1));
    }
}

// ---------------- launch ----------------
extern "C" void kernel_launch(void* const* d_in, const int* in_sizes, int n_in,
                              void* d_out, int out_size) {
    const float* windows = (const float*)d_in[0];
    const float* Wih_f   = (const float*)d_in[1];
    const float* Whh_f   = (const float*)d_in[2];
    const float* bih_f   = (const float*)d_in[3];
    const float* bhh_f   = (const float*)d_in[4];
    const float* Wih_b   = (const float*)d_in[5];
    const float* Whh_b   = (const float*)d_in[6];
    const float* bih_b   = (const float*)d_in[7];
    const float* bhh_b   = (const float*)d_in[8];
    float* out = (float*)d_out;

    const int PERSIST_SMEM = (48 * WS_STRIDE + 2 * Bb * AS_STRIDE) * 2;
    static int attr_set = 0;
    if (!attr_set) {
        cudaFuncSetAttribute(k_persist, cudaFuncAttributeMaxDynamicSharedMemorySize, PERSIST_SMEM);
        attr_set = 1;
    }

    const int wthreads = 256;
    const int wtotal = 3 * HP * HP;
    prep_w<<<(wtotal + wthreads - 1) / wthreads, wthreads>>>(Wih_f, Whh_f, bih_f, bhh_f, 0);
    prep_w<<<(wtotal + wthreads - 1) / wthreads, wthreads>>>(Wih_b, Whh_b, bih_b, bhh_b, 1);

    const int xtotal = TB * (HP / 4);
    prep_x<<<(xtotal + 255) / 256, 256>>>(windows);

    const int htotal = 2 * 2 * Bb * HP;
    zero_h<<<(htotal + 255) / 256, 256>>>();

    k_gi<<<dim3(6, 512, 6), 256>>>();

    k_persist<<<NCTA, 256, PERSIST_SMEM>>>(windows, out);
}

// round 6
// speedup vs baseline: 2.0778x; 1.0840x over previous
#include <cuda_runtime.h>
#include <cuda_fp16.h>
#include <cstdint>

#define Hh   744
#define HP   768
#define Bb   256
#define Tt   256
#define Cc   16
#define WIN  800
#define TB   (Tt*Bb)          // 65536
#define OUTT (Tt - 2*Cc)      // 224
#define OUTW (2*Hh)           // 1488

#define NJT    48
#define JT     16
#define NCTA   (2*NJT)
#define WS_STRIDE 776         // halfs: 768 + 8 pad
#define KC     64             // persist k-chunk
#define AS_STRIDE 72          // halfs: 64 + 8 pad
#define GI_AST    40          // halfs

// ---------------- scratch ----------------
__device__ __half g_Wi16[2][3][HP][HP];
__device__ __half g_Wh16[2][3][HP][HP];
__device__ float  g_bi[2][3][HP];
__device__ float  g_bh[2][3][HP];
__device__ __half g_X16[TB][HP];
__device__ float  g_GI[2][3][TB][HP];
__device__ float  g_h  [2][2][Bb][HP];
__device__ __half g_h16[2][2][Bb][HP];
__device__ unsigned g_bar;
__device__ unsigned g_ready[2][Tt];      // plane-done flags
__device__ unsigned g_pcnt[2][Tt];       // plane CTA counters

// ---------------- helpers ----------------
__device__ __forceinline__ float sigf(float x) { return 1.0f / (1.0f + __expf(-x)); }
__device__ __forceinline__ float tanh_fast(float x) {
    x = fminf(15.0f, fmaxf(-15.0f, x));
    float e = __expf(2.0f * x);
    return (e - 1.0f) / (e + 1.0f);
}
__device__ __forceinline__ void mma_fp16(float* c, const uint32_t* a, const uint32_t* b) {
    asm volatile(
        "mma.sync.aligned.m16n8k16.row.col.f32.f16.f16.f32 "
        "{%0,%1,%2,%3},{%4,%5,%6,%7},{%8,%9},{%0,%1,%2,%3};\n"
        : "+f"(c[0]), "+f"(c[1]), "+f"(c[2]), "+f"(c[3])
        : "r"(a[0]), "r"(a[1]), "r"(a[2]), "r"(a[3]), "r"(b[0]), "r"(b[1]));
}
__device__ __forceinline__ void cp16h(__half* s, const __half* g) {
    uint32_t sa = (uint32_t)__cvta_generic_to_shared(s);
    asm volatile("cp.async.cg.shared.global [%0], [%1], 16;" :: "r"(sa), "l"(g));
}
__device__ __forceinline__ uint32_t s2u(const void* p) {
    return (uint32_t)__cvta_generic_to_shared(p);
}
__device__ __forceinline__ void ldsm4(uint32_t* r, uint32_t addr) {
    asm volatile("ldmatrix.sync.aligned.m8n8.x4.shared.b16 {%0,%1,%2,%3}, [%4];"
        : "=r"(r[0]), "=r"(r[1]), "=r"(r[2]), "=r"(r[3]) : "r"(addr));
}

// ---------------- prep kernels ----------------
__global__ void prep_w(const float* __restrict__ Wih, const float* __restrict__ Whh,
                       const float* __restrict__ bih, const float* __restrict__ bhh, int d) {
    int idx = blockIdx.x * blockDim.x + threadIdx.x;
    const int total = 3 * HP * HP;
    if (idx < total) {
        int g = idx / (HP * HP);
        int rem = idx % (HP * HP);
        int j = rem / HP;
        int k = rem % HP;
        float wi = 0.0f, wh = 0.0f;
        if (j < Hh && k < Hh) {
            wi = Wih[(size_t)(g * Hh + j) * Hh + k];
            wh = Whh[(size_t)(g * Hh + j) * Hh + k];
        }
        g_Wi16[d][g][j][k] = __float2half_rn(wi);
        g_Wh16[d][g][j][k] = __float2half_rn(wh);
    }
    if (idx < 3 * HP) {
        int g = idx / HP, j = idx % HP;
        float bi = 0.0f, bh = 0.0f;
        if (j < Hh) { bi = bih[g * Hh + j]; bh = bhh[g * Hh + j]; }
        g_bi[d][g][j] = bi;
        g_bh[d][g][j] = bh;
    }
}

__global__ void prep_x(const float* __restrict__ win) {
    int idx = blockIdx.x * blockDim.x + threadIdx.x;
    const int total = TB * (HP / 4);
    if (idx >= total) return;
    int row = idx / (HP / 4);
    int kq  = idx % (HP / 4);
    int k = kq * 4;
    int t = row / Bb, b = row % Bb;
    float4 v = make_float4(0.f, 0.f, 0.f, 0.f);
    if (k < Hh) {
        v = *(const float4*)(win + (size_t)b * Tt * WIN + (size_t)t * WIN + k);
    }
    __half2* dst = (__half2*)&g_X16[row][k];
    dst[0] = __floats2half2_rn(v.x, v.y);
    dst[1] = __floats2half2_rn(v.z, v.w);
}

__global__ void zero_h() {
    int idx = blockIdx.x * blockDim.x + threadIdx.x;
    const int total = 2 * 2 * Bb * HP;
    if (idx < total) ((float*)g_h)[idx] = 0.0f;
    if (idx < total / 2) ((uint32_t*)g_h16)[idx] = 0u;
    if (idx < 2 * Tt) { ((unsigned*)g_ready)[idx] = 0u; ((unsigned*)g_pcnt)[idx] = 0u; }
    if (idx == 0) g_bar = 0u;
}

// ---------------- K1: GI = X @ Wih^T + bih ----------------
// grid (36, 512): x = d*18 + g*6 + nt; y = ti*2 + half, t ordered outward-in
__global__ void __launch_bounds__(256, 2) k_gi() {
    __shared__ __half As[2][128][GI_AST];
    __shared__ __half Bs[2][128][GI_AST];

    const int tid  = threadIdx.x;
    const int lane = tid & 31;
    const int w    = tid >> 5;
    const int grp  = lane >> 2;
    const int tg   = lane & 3;
    const int wm   = w >> 1;
    const int wn   = w & 1;

    const int bx  = blockIdx.x;
    const int d   = bx / 18;
    const int rem = bx % 18;
    const int g   = rem / 6;
    const int nt  = rem % 6;
    const int j0  = nt * 128;

    const int ti   = blockIdx.y >> 1;
    const int halfb = blockIdx.y & 1;
    const int t    = (ti & 1) ? (Tt - 1 - (ti >> 1)) : (ti >> 1);
    const int row0 = t * Bb + halfb * 128;

    const __half* __restrict__ Ag = &g_X16[row0][0];
    const __half* __restrict__ Bg = &g_Wi16[d][g][j0][0];

    const int a_row  = lane & 15;
    const int a_koff = (lane >> 4) * 8;
    const int b_row  = ((lane >> 4)) * 8 + (lane & 7);
    const int b_koff = ((lane >> 3) & 1) * 8;

    float acc[8][2][4];
#pragma unroll
    for (int nf = 0; nf < 8; nf++)
#pragma unroll
        for (int mi = 0; mi < 2; mi++)
#pragma unroll
            for (int i = 0; i < 4; i++) acc[nf][mi][i] = 0.0f;

    const uint32_t as_u[2] = { s2u(&As[0][0][0]), s2u(&As[1][0][0]) };
    const uint32_t bs_u[2] = { s2u(&Bs[0][0][0]), s2u(&Bs[1][0][0]) };
    const uint32_t a_off = ((wm * 32 + a_row) * GI_AST + a_koff) * 2;
    const uint32_t b_off = ((wn * 64 + b_row) * GI_AST + b_koff) * 2;

    auto loadstage = [&](int kt, int s) {
        const int k0 = kt * 32;
#pragma unroll
        for (int i = 0; i < 2; i++) {
            int li = tid + i * 256;
            int r = li >> 2, kq = li & 3;
            cp16h(&As[s][r][kq * 8], Ag + (size_t)r * HP + k0 + kq * 8);
        }
#pragma unroll
        for (int i = 0; i < 2; i++) {
            int li = tid + i * 256;
            int r = li >> 2, kq = li & 3;
            cp16h(&Bs[s][r][kq * 8], Bg + (size_t)r * HP + k0 + kq * 8);
        }
        asm volatile("cp.async.commit_group;");
    };

    loadstage(0, 0);

    for (int kt = 0; kt < HP / 32; kt++) {
        const int s = kt & 1;
        if (kt < HP / 32 - 1) {
            loadstage(kt + 1, s ^ 1);
            asm volatile("cp.async.wait_group 1;");
        } else {
            asm volatile("cp.async.wait_group 0;");
        }
        __syncthreads();

        const uint32_t ab = as_u[s] + a_off;
        const uint32_t bb = bs_u[s] + b_off;
#pragma unroll
        for (int kk = 0; kk < 2; kk++) {
            uint32_t af[2][4];
            ldsm4(af[0], ab + kk * 32);
            ldsm4(af[1], ab + 16 * GI_AST * 2 + kk * 32);
#pragma unroll
            for (int p = 0; p < 4; p++) {
                uint32_t bf[4];
                ldsm4(bf, bb + p * 16 * GI_AST * 2 + kk * 32);
                mma_fp16(acc[2 * p][0],     af[0], bf);
                mma_fp16(acc[2 * p][1],     af[1], bf);
                mma_fp16(acc[2 * p + 1][0], af[0], bf + 2);
                mma_fp16(acc[2 * p + 1][1], af[1], bf + 2);
            }
        }
        __syncthreads();
    }

    float* __restrict__ GIp = &g_GI[d][g][0][0];
    const float* __restrict__ bip = &g_bi[d][g][0];
#pragma unroll
    for (int mi = 0; mi < 2; mi++) {
#pragma unroll
        for (int nf = 0; nf < 8; nf++) {
            int r = row0 + wm * 32 + mi * 16 + grp;
            int j = j0 + wn * 64 + nf * 8 + tg * 2;
            float b0 = bip[j], b1 = bip[j + 1];
            float* a = acc[nf][mi];
            GIp[(size_t)r * HP + j]           = a[0] + b0;
            GIp[(size_t)r * HP + j + 1]       = a[1] + b1;
            GIp[(size_t)(r + 8) * HP + j]     = a[2] + b0;
            GIp[(size_t)(r + 8) * HP + j + 1] = a[3] + b1;
        }
    }

    // plane completion: 36 CTAs per (d, t)
    __syncthreads();
    if (tid == 0) {
        __threadfence();
        unsigned old = atomicAdd(&g_pcnt[d][t], 1u);
        if (old == 35u) {
            asm volatile("st.release.gpu.global.u32 [%0], %1;"
                         :: "l"(&g_ready[d][t]), "r"(1u) : "memory");
        }
    }
}

// ---------------- persistent recurrent kernel ----------------
__device__ __forceinline__ void gbar(unsigned expect) {
    __syncthreads();
    if (threadIdx.x == 0) {
        asm volatile("red.release.gpu.global.add.u32 [%0], 1;" :: "l"(&g_bar) : "memory");
        unsigned v;
        do {
            asm volatile("ld.acquire.gpu.global.u32 %0, [%1];" : "=r"(v) : "l"(&g_bar));
        } while (v < expect);
    }
    __syncthreads();
}

__global__ void __launch_bounds__(256, 1)
k_persist(const float* __restrict__ win, float* __restrict__ out) {
    extern __shared__ __half smemh[];
    __half* Ws  = smemh;                          // [48][776]
    __half* As0 = smemh + 48 * WS_STRIDE;         // [256][72]
    __half* As1 = As0 + Bb * AS_STRIDE;

    const int tid  = threadIdx.x;
    const int lane = tid & 31;
    const int w    = tid >> 5;
    const int grp  = lane >> 2;
    const int tg   = lane & 3;
    const int m0w  = w * 32;

    const int d  = blockIdx.x / NJT;
    const int j0 = (blockIdx.x % NJT) * JT;

    {
        const __half* src = &g_Wh16[d][0][0][0];
        for (int idx = tid; idx < 48 * (HP / 8); idx += 256) {
            int c = idx / (HP / 8);
            int k8 = (idx % (HP / 8)) * 8;
            int g = c / JT, jj = c % JT;
            *(uint4*)&Ws[c * WS_STRIDE + k8] =
                *(const uint4*)(src + ((size_t)g * HP + (j0 + jj)) * HP + k8);
        }
    }
    __syncthreads();

    const int a_row  = lane & 15;
    const int a_koff = (lane >> 4) * 8;
    const int b_row  = ((lane >> 4)) * 8 + (lane & 7);
    const int b_koff = ((lane >> 3) & 1) * 8;

    const uint32_t asu[2] = { s2u(As0), s2u(As1) };
    const uint32_t a_off = ((m0w + a_row) * AS_STRIDE + a_koff) * 2;
    uint32_t wsp[3];
#pragma unroll
    for (int p = 0; p < 3; p++)
        wsp[p] = s2u(Ws) + ((p * 16 + b_row) * WS_STRIDE + b_koff) * 2;

    const size_t PLANE = (size_t)TB * HP;
    const float* __restrict__ GI0 = &g_GI[d][0][0][0];
    const float* __restrict__ bh0 = &g_bh[d][0][0];

    for (int t = 0; t < Tt; t++) {
        const int p  = t & 1;
        const int xt = (d == 0) ? t : (Tt - 1 - t);
        const __half* __restrict__ hA = &g_h16[p][d][0][0];

        float acc[6][2][4];
#pragma unroll
        for (int nf = 0; nf < 6; nf++)
#pragma unroll
            for (int mi = 0; mi < 2; mi++)
#pragma unroll
                for (int i = 0; i < 4; i++) acc[nf][mi][i] = 0.0f;

        // preload chunk 0: 256 rows x 64 halfs = 2048 x 16B / 256 thr
        {
#pragma unroll
            for (int i = 0; i < 8; i++) {
                int li = tid + i * 256;
                int r = li >> 3, kq = li & 7;
                cp16h(&As0[r * AS_STRIDE + kq * 8], hA + (size_t)r * HP + kq * 8);
            }
            asm volatile("cp.async.commit_group;");
        }

        for (int kt = 0; kt < HP / KC; kt++) {
            const int k0 = kt * KC;
            const int s = kt & 1;
            if (kt < HP / KC - 1) {
                __half* Anext = s ? As0 : As1;
                const int kn = k0 + KC;
#pragma unroll
                for (int i = 0; i < 8; i++) {
                    int li = tid + i * 256;
                    int r = li >> 3, kq = li & 7;
                    cp16h(&Anext[r * AS_STRIDE + kq * 8], hA + (size_t)r * HP + kn + kq * 8);
                }
                asm volatile("cp.async.commit_group;");
                asm volatile("cp.async.wait_group 1;");
            } else {
                asm volatile("cp.async.wait_group 0;");
            }
            __syncthreads();

            const uint32_t ab = asu[s] + a_off;
#pragma unroll
            for (int kk = 0; kk < 4; kk++) {
                uint32_t af[2][4];
                ldsm4(af[0], ab + kk * 32);
                ldsm4(af[1], ab + 16 * AS_STRIDE * 2 + kk * 32);
#pragma unroll
                for (int pg = 0; pg < 3; pg++) {
                    uint32_t bf[4];
                    ldsm4(bf, wsp[pg] + (k0 + kk * 16) * 2);
                    mma_fp16(acc[2 * pg][0],     af[0], bf);
                    mma_fp16(acc[2 * pg][1],     af[1], bf);
                    mma_fp16(acc[2 * pg + 1][0], af[0], bf + 2);
                    mma_fp16(acc[2 * pg + 1][1], af[1], bf + 2);
                }
            }
            __syncthreads();
        }

        // wait for this step's GI plane (producer = concurrent k_gi)
        if (tid == 0) {
            unsigned v;
            while (true) {
                asm volatile("ld.acquire.gpu.global.u32 %0, [%1];"
                             : "=r"(v) : "l"(&g_ready[d][xt]));
                if (v) break;
                __nanosleep(200);
            }
        }
        __syncthreads();

        // ---- fused GRU epilogue ----
        const bool doOut = (t >= Cc) && (t < Tt - Cc);
        const float*  __restrict__ hin    = &g_h[p][d][0][0];
        float*  __restrict__ hout         = &g_h[p ^ 1][d][0][0];
        __half* __restrict__ hout16       = &g_h16[p ^ 1][d][0][0];

#pragma unroll
        for (int mi = 0; mi < 2; mi++) {
#pragma unroll
            for (int nf0 = 0; nf0 < 2; nf0++) {
                const int jj = nf0 * 8 + tg * 2;
                const int j  = j0 + jj;
                const float br0 = bh0[j],            br1 = bh0[j + 1];
                const float bz0 = bh0[HP + j],       bz1 = bh0[HP + j + 1];
                const float bn0 = bh0[2 * HP + j],   bn1 = bh0[2 * HP + j + 1];
#pragma unroll
                for (int half2i = 0; half2i < 2; half2i++) {
                    const int b  = m0w + mi * 16 + grp + half2i * 8;
                    const int ai = half2i * 2;
                    const float aR0 = acc[nf0][mi][ai],     aR1 = acc[nf0][mi][ai + 1];
                    const float aZ0 = acc[nf0 + 2][mi][ai], aZ1 = acc[nf0 + 2][mi][ai + 1];
                    const float aN0 = acc[nf0 + 4][mi][ai], aN1 = acc[nf0 + 4][mi][ai + 1];

                    const size_t gio = (size_t)(xt * Bb + b) * HP + j;
                    const float gr0 = __ldcg(&GI0[gio]);
                    const float gr1 = __ldcg(&GI0[gio + 1]);
                    const float gz0 = __ldcg(&GI0[PLANE + gio]);
                    const float gz1 = __ldcg(&GI0[PLANE + gio + 1]);
                    const float gn0 = __ldcg(&GI0[2 * PLANE + gio]);
                    const float gn1 = __ldcg(&GI0[2 * PLANE + gio + 1]);

                    const float ho0 = __ldcg(&hin[(size_t)b * HP + j]);
                    const float ho1 = __ldcg(&hin[(size_t)b * HP + j + 1]);

                    const float r0 = sigf(gr0 + aR0 + br0);
                    const float r1 = sigf(gr1 + aR1 + br1);
                    const float z0 = sigf(gz0 + aZ0 + bz0);
                    const float z1 = sigf(gz1 + aZ1 + bz1);
                    const float n0 = tanh_fast(gn0 + r0 * (aN0 + bn0));
                    const float n1 = tanh_fast(gn1 + r1 * (aN1 + bn1));
                    const float h0 = (1.0f - z0) * n0 + z0 * ho0;
                    const float h1 = (1.0f - z1) * n1 + z1 * ho1;

                    hout[(size_t)b * HP + j]     = h0;
                    hout[(size_t)b * HP + j + 1] = h1;
                    *(__half2*)&hout16[(size_t)b * HP + j] = __floats2half2_rn(h0, h1);

                    if (doOut && j < Hh) {
                        const size_t xo = (size_t)b * Tt * WIN + (size_t)xt * WIN + j;
                        const size_t oo = (size_t)b * (OUTT * OUTW) + (size_t)(t - Cc) * OUTW + d * Hh + j;
                        out[oo]     = h0 + win[xo];
                        out[oo + 1] = h1 + win[xo + 1];
                    }
                }
            }
        }

        gbar((unsigned)NCTA * (unsigned)(t + 1));
    }
}

// ---------------- launch ----------------
extern "C" void kernel_launch(void* const* d_in, const int* in_sizes, int n_in,
                              void* d_out, int out_size) {
    const float* windows = (const float*)d_in[0];
    const float* Wih_f   = (const float*)d_in[1];
    const float* Whh_f   = (const float*)d_in[2];
    const float* bih_f   = (const float*)d_in[3];
    const float* bhh_f   = (const float*)d_in[4];
    const float* Wih_b   = (const float*)d_in[5];
    const float* Whh_b   = (const float*)d_in[6];
    const float* bih_b   = (const float*)d_in[7];
    const float* bhh_b   = (const float*)d_in[8];
    float* out = (float*)d_out;

    const int PERSIST_SMEM = (48 * WS_STRIDE + 2 * Bb * AS_STRIDE) * 2;  // 148224 B

    static cudaStream_t s2 = nullptr;
    static cudaEvent_t  eA = nullptr, eB = nullptr;
    static int init_done = 0;
    if (!init_done) {
        cudaFuncSetAttribute(k_persist, cudaFuncAttributeMaxDynamicSharedMemorySize, PERSIST_SMEM);
        cudaStreamCreateWithFlags(&s2, cudaStreamNonBlocking);
        cudaEventCreateWithFlags(&eA, cudaEventDisableTiming);
        cudaEventCreateWithFlags(&eB, cudaEventDisableTiming);
        init_done = 1;
    }

    const int wthreads = 256;
    const int wtotal = 3 * HP * HP;
    prep_w<<<(wtotal + wthreads - 1) / wthreads, wthreads>>>(Wih_f, Whh_f, bih_f, bhh_f, 0);
    prep_w<<<(wtotal + wthreads - 1) / wthreads, wthreads>>>(Wih_b, Whh_b, bih_b, bhh_b, 1);

    const int xtotal = TB * (HP / 4);
    prep_x<<<(xtotal + 255) / 256, 256>>>(windows);

    const int htotal = 2 * 2 * Bb * HP;
    zero_h<<<(htotal + 255) / 256, 256>>>();

    // fork: k_gi on s2 concurrent with k_persist on the main stream
    cudaEventRecord(eA, 0);
    cudaStreamWaitEvent(s2, eA, 0);
    k_gi<<<dim3(36, 512), 256, 0, s2>>>();
    cudaEventRecord(eB, s2);

    k_persist<<<NCTA, 256, PERSIST_SMEM>>>(windows, out);

    // join
    cudaStreamWaitEvent(0, eB, 0);
}

// round 7
// speedup vs baseline: 2.4149x; 1.1623x over previous
#include <cuda_runtime.h>
#include <cuda_fp16.h>
#include <cstdint>

#define Hh   744
#define HP   768
#define Bb   256
#define Tt   256
#define Cc   16
#define WIN  800
#define TB   (Tt*Bb)          // 65536
#define OUTT (Tt - 2*Cc)      // 224
#define OUTW (2*Hh)           // 1488

#define NJT    48
#define JT     16
#define NCTA   (2*NJT)
#define WS_STRIDE 776         // halfs: 768 + 8 pad (persist weights, linear)
#define KC     64             // k-chunk (both kernels)
#define NCH    (HP/KC)        // 12
#define PCHUNK 32768          // persist chunk bytes: 256 rows x 128B
#define GCHUNK 16384          // k_gi tile chunk bytes: 128 rows x 128B

// ---------------- scratch ----------------
__device__ __half g_Wic[6][NCH][HP][KC];      // chunked+swizzled input weights
__device__ __half g_Wh16[2][3][HP][HP];       // linear recurrent weights (smem-resident)
__device__ float  g_bi[2][3][HP];
__device__ float  g_bh[2][3][HP];
__device__ __half g_Xc[NCH][TB][KC];          // chunked+swizzled x
__device__ float  g_GI[2][3][TB][HP];
__device__ float  g_h [2][2][Bb][HP];         // fp32 carried state (linear)
__device__ __half g_hc[2][2][NCH][Bb][KC];    // chunked+swizzled fp16 h mirror
__device__ unsigned g_bar;
__device__ unsigned g_ready[2][Tt];
__device__ unsigned g_pcnt[2][Tt];

// ---------------- helpers ----------------
__device__ __forceinline__ float sigf(float x) { return 1.0f / (1.0f + __expf(-x)); }
__device__ __forceinline__ float tanh_fast(float x) {
    x = fminf(15.0f, fmaxf(-15.0f, x));
    float e = __expf(2.0f * x);
    return (e - 1.0f) / (e + 1.0f);
}
__device__ __forceinline__ void mma_fp16(float* c, const uint32_t* a, const uint32_t* b) {
    asm volatile(
        "mma.sync.aligned.m16n8k16.row.col.f32.f16.f16.f32 "
        "{%0,%1,%2,%3},{%4,%5,%6,%7},{%8,%9},{%0,%1,%2,%3};\n"
        : "+f"(c[0]), "+f"(c[1]), "+f"(c[2]), "+f"(c[3])
        : "r"(a[0]), "r"(a[1]), "r"(a[2]), "r"(a[3]), "r"(b[0]), "r"(b[1]));
}
__device__ __forceinline__ uint32_t s2u(const void* p) {
    return (uint32_t)__cvta_generic_to_shared(p);
}
__device__ __forceinline__ void ldsm4(uint32_t* r, uint32_t addr) {
    asm volatile("ldmatrix.sync.aligned.m8n8.x4.shared.b16 {%0,%1,%2,%3}, [%4];"
        : "=r"(r[0]), "=r"(r[1]), "=r"(r[2]), "=r"(r[3]) : "r"(addr));
}
#define MBAR_INIT(addr, cnt) \
    asm volatile("mbarrier.init.shared.b64 [%0], %1;" :: "r"(addr), "r"(cnt) : "memory")
#define MBAR_WAIT(addr, par) do { \
    asm volatile("{.reg .pred P1; WL%=: mbarrier.try_wait.parity.acquire.cta.shared::cta.b64 P1, [%0], %1, 0x989680; @P1 bra.uni WD%=; bra.uni WL%=; WD%=:}" \
        :: "r"(addr), "r"(par) : "memory"); \
} while (0)
__device__ __forceinline__ void bulk_ld(uint32_t dst, const void* src, uint32_t bytes, uint32_t mb) {
    asm volatile("cp.async.bulk.shared::cta.global.mbarrier::complete_tx::bytes [%0], [%1], %2, [%3];"
        :: "r"(dst), "l"(src), "r"(bytes), "r"(mb) : "memory");
}
__device__ __forceinline__ void expect_tx(uint32_t mb, uint32_t bytes) {
    asm volatile("mbarrier.arrive.expect_tx.shared.b64 _, [%0], %1;"
        :: "r"(mb), "r"(bytes) : "memory");
}

// ---------------- prep kernels ----------------
__global__ void prep_w(const float* __restrict__ Wih, const float* __restrict__ Whh,
                       const float* __restrict__ bih, const float* __restrict__ bhh, int d) {
    int idx = blockIdx.x * blockDim.x + threadIdx.x;
    const int total = 3 * HP * HP;
    if (idx < total) {
        int g = idx / (HP * HP);
        int rem = idx % (HP * HP);
        int j = rem / HP;
        int k = rem % HP;
        float wi = 0.0f, wh = 0.0f;
        if (j < Hh && k < Hh) {
            wi = Wih[(size_t)(g * Hh + j) * Hh + k];
            wh = Whh[(size_t)(g * Hh + j) * Hh + k];
        }
        // Wi: chunked + swizzled
        int dg = d * 3 + g;
        int ch = k / KC, kc = k % KC;
        size_t off = (((size_t)dg * NCH + ch) * HP + j) * 128 + (((unsigned)(kc * 2)) ^ ((j & 7) << 4));
        *(__half*)((char*)g_Wic + off) = __float2half_rn(wi);
        // Wh: linear
        g_Wh16[d][g][j][k] = __float2half_rn(wh);
    }
    if (idx < 3 * HP) {
        int g = idx / HP, j = idx % HP;
        float bi = 0.0f, bh = 0.0f;
        if (j < Hh) { bi = bih[g * Hh + j]; bh = bhh[g * Hh + j]; }
        g_bi[d][g][j] = bi;
        g_bh[d][g][j] = bh;
    }
}

__global__ void prep_x(const float* __restrict__ win) {
    int idx = blockIdx.x * blockDim.x + threadIdx.x;
    const int total = TB * (HP / 4);
    if (idx >= total) return;
    int row = idx / (HP / 4);
    int kq  = idx % (HP / 4);
    int k = kq * 4;
    int t = row / Bb, b = row % Bb;
    float4 v = make_float4(0.f, 0.f, 0.f, 0.f);
    if (k < Hh) {
        v = *(const float4*)(win + (size_t)b * Tt * WIN + (size_t)t * WIN + k);
    }
    int ch = k / KC, kc = k % KC;
    size_t off = ((size_t)ch * TB + row) * 128 + (((unsigned)(kc * 2)) ^ ((row & 7) << 4));
    __half2* dst = (__half2*)((char*)g_Xc + off);
    dst[0] = __floats2half2_rn(v.x, v.y);
    dst[1] = __floats2half2_rn(v.z, v.w);
}

__global__ void zero_h() {
    int idx = blockIdx.x * blockDim.x + threadIdx.x;
    const int total = 2 * 2 * Bb * HP;
    if (idx < total) ((float*)g_h)[idx] = 0.0f;
    if (idx < total / 2) ((uint32_t*)g_hc)[idx] = 0u;
    if (idx < 2 * Tt) { ((unsigned*)g_ready)[idx] = 0u; ((unsigned*)g_pcnt)[idx] = 0u; }
    if (idx == 0) g_bar = 0u;
}

// ---------------- K1: GI = X @ Wih^T + bih (bulk-DMA loads) ----------------
// grid (36, 512): x = d*18 + g*6 + nt; y: t outward-in, halves
// smem: [0]=mbar0 [8]=mbar1 | 1024: A0(16K) B0(16K) A1(16K) B1(16K)
#define GI_SMEM (1024 + 4 * GCHUNK)
__global__ void __launch_bounds__(256, 2) k_gi() {
    extern __shared__ __align__(1024) char smem[];
    const uint32_t sb = s2u(smem);

    const int tid  = threadIdx.x;
    const int lane = tid & 31;
    const int w    = tid >> 5;
    const int grp  = lane >> 2;
    const int tg   = lane & 3;
    const int wm   = w >> 1;
    const int wn   = w & 1;

    const int bx  = blockIdx.x;
    const int d   = bx / 18;
    const int rem = bx % 18;
    const int g   = rem / 6;
    const int nt  = rem % 6;
    const int j0  = nt * 128;
    const int dg  = d * 3 + g;

    const int ti    = blockIdx.y >> 1;
    const int halfb = blockIdx.y & 1;
    const int t     = (ti & 1) ? (Tt - 1 - (ti >> 1)) : (ti >> 1);
    const int row0  = t * Bb + halfb * 128;

    if (tid == 0) { MBAR_INIT(sb, 1); MBAR_INIT(sb + 8, 1); }
    __syncthreads();

    // fragment address precompute
    const int arow  = wm * 32 + (lane & 15);
    const uint32_t arb  = (uint32_t)arow * 128;
    const uint32_t axor = (uint32_t)(arow & 7) << 4;
    const uint32_t acl  = (uint32_t)(lane >> 4) << 4;
    const int brow  = wn * 64 + (lane >> 4) * 8 + (lane & 7);
    const uint32_t brb  = (uint32_t)brow * 128;
    const uint32_t bxor = (uint32_t)(brow & 7) << 4;
    const uint32_t bcl  = (uint32_t)((lane >> 3) & 1) << 4;

    float acc[8][2][4];
#pragma unroll
    for (int nf = 0; nf < 8; nf++)
#pragma unroll
        for (int mi = 0; mi < 2; mi++)
#pragma unroll
            for (int i = 0; i < 4; i++) acc[nf][mi][i] = 0.0f;

    auto issue = [&](int c) {
        if (tid == 0) {
            const int s = c & 1;
            const uint32_t mb = sb + s * 8;
            expect_tx(mb, 2 * GCHUNK);
            bulk_ld(sb + 1024 + s * 2 * GCHUNK,
                    (const char*)g_Xc + ((size_t)c * TB + row0) * 128, GCHUNK, mb);
            bulk_ld(sb + 1024 + s * 2 * GCHUNK + GCHUNK,
                    (const char*)g_Wic + (((size_t)dg * NCH + c) * HP + j0) * 128, GCHUNK, mb);
        }
    };

    int ph[2] = {0, 0};
    issue(0);

    for (int kt = 0; kt < NCH; kt++) {
        const int s = kt & 1;
        if (kt < NCH - 1) issue(kt + 1);
        MBAR_WAIT(sb + s * 8, ph[s]);
        ph[s] ^= 1;

        const uint32_t abuf = sb + 1024 + s * 2 * GCHUNK;
        const uint32_t bbuf = abuf + GCHUNK;
#pragma unroll
        for (int kk = 0; kk < 4; kk++) {
            const uint32_t ac = ((uint32_t)(kk * 32) + acl) ^ axor;
            const uint32_t bc = ((uint32_t)(kk * 32) + bcl) ^ bxor;
            uint32_t af[2][4];
            ldsm4(af[0], abuf + arb + ac);
            ldsm4(af[1], abuf + arb + 2048 + ac);
#pragma unroll
            for (int p = 0; p < 4; p++) {
                uint32_t bf[4];
                ldsm4(bf, bbuf + brb + p * 2048 + bc);
                mma_fp16(acc[2 * p][0],     af[0], bf);
                mma_fp16(acc[2 * p][1],     af[1], bf);
                mma_fp16(acc[2 * p + 1][0], af[0], bf + 2);
                mma_fp16(acc[2 * p + 1][1], af[1], bf + 2);
            }
        }
        __syncthreads();
    }

    float* __restrict__ GIp = &g_GI[d][g][0][0];
    const float* __restrict__ bip = &g_bi[d][g][0];
#pragma unroll
    for (int mi = 0; mi < 2; mi++) {
#pragma unroll
        for (int nf = 0; nf < 8; nf++) {
            int r = row0 + wm * 32 + mi * 16 + grp;
            int j = j0 + wn * 64 + nf * 8 + tg * 2;
            float b0 = bip[j], b1 = bip[j + 1];
            float* a = acc[nf][mi];
            GIp[(size_t)r * HP + j]           = a[0] + b0;
            GIp[(size_t)r * HP + j + 1]       = a[1] + b1;
            GIp[(size_t)(r + 8) * HP + j]     = a[2] + b0;
            GIp[(size_t)(r + 8) * HP + j + 1] = a[3] + b1;
        }
    }

    __syncthreads();
    if (tid == 0) {
        __threadfence();
        unsigned old = atomicAdd(&g_pcnt[d][t], 1u);
        if (old == 35u) {
            asm volatile("st.release.gpu.global.u32 [%0], %1;"
                         :: "l"(&g_ready[d][t]), "r"(1u) : "memory");
        }
    }
}

// ---------------- persistent recurrent kernel (bulk-DMA A loads) ----------------
__device__ __forceinline__ void gbar(unsigned expect) {
    __syncthreads();
    if (threadIdx.x == 0) {
        asm volatile("red.release.gpu.global.add.u32 [%0], 1;" :: "l"(&g_bar) : "memory");
        unsigned v;
        do {
            asm volatile("ld.acquire.gpu.global.u32 %0, [%1];" : "=r"(v) : "l"(&g_bar));
        } while (v < expect);
    }
    __syncthreads();
}

// smem: [0]=mbar0 [8]=mbar1 | 1024: A0(32K) A1(32K) | 66560: Ws(74496)
#define P_WSOFF 66560
#define P_SMEM  (P_WSOFF + 48 * WS_STRIDE * 2)   // 141056
__global__ void __launch_bounds__(256, 1)
k_persist(const float* __restrict__ win, float* __restrict__ out) {
    extern __shared__ __align__(1024) char smem[];
    const uint32_t sb = s2u(smem);
    __half* Ws = (__half*)(smem + P_WSOFF);

    const int tid  = threadIdx.x;
    const int lane = tid & 31;
    const int w    = tid >> 5;
    const int grp  = lane >> 2;
    const int tg   = lane & 3;
    const int m0w  = w * 32;

    const int d  = blockIdx.x / NJT;
    const int j0 = (blockIdx.x % NJT) * JT;

    if (tid == 0) { MBAR_INIT(sb, 1); MBAR_INIT(sb + 8, 1); }

    {
        const __half* src = &g_Wh16[d][0][0][0];
        for (int idx = tid; idx < 48 * (HP / 8); idx += 256) {
            int c = idx / (HP / 8);
            int k8 = (idx % (HP / 8)) * 8;
            int g = c / JT, jj = c % JT;
            *(uint4*)&Ws[c * WS_STRIDE + k8] =
                *(const uint4*)(src + ((size_t)g * HP + (j0 + jj)) * HP + k8);
        }
    }
    __syncthreads();

    // fragment address precompute
    const int arow  = m0w + (lane & 15);
    const uint32_t arb  = (uint32_t)arow * 128;
    const uint32_t axor = (uint32_t)(arow & 7) << 4;
    const uint32_t acl  = (uint32_t)(lane >> 4) << 4;

    const int b_row  = (lane >> 4) * 8 + (lane & 7);
    const int b_koff = ((lane >> 3) & 1) * 8;
    uint32_t wsp[3];
#pragma unroll
    for (int p = 0; p < 3; p++)
        wsp[p] = s2u(Ws) + ((p * 16 + b_row) * WS_STRIDE + b_koff) * 2;

    const size_t PLANE = (size_t)TB * HP;
    const float* __restrict__ GI0 = &g_GI[d][0][0][0];
    const float* __restrict__ bh0 = &g_bh[d][0][0];

    int ph[2] = {0, 0};

    for (int t = 0; t < Tt; t++) {
        const int p  = t & 1;
        const int xt = (d == 0) ? t : (Tt - 1 - t);
        const char* hcbase = (const char*)&g_hc[p][d][0][0][0];

        float acc[6][2][4];
#pragma unroll
        for (int nf = 0; nf < 6; nf++)
#pragma unroll
            for (int mi = 0; mi < 2; mi++)
#pragma unroll
                for (int i = 0; i < 4; i++) acc[nf][mi][i] = 0.0f;

        auto issue = [&](int c) {
            if (tid == 0) {
                const int s = c & 1;
                const uint32_t mb = sb + s * 8;
                expect_tx(mb, PCHUNK);
                bulk_ld(sb + 1024 + s * PCHUNK, hcbase + (size_t)c * PCHUNK, PCHUNK, mb);
            }
        };

        issue(0);
        for (int kt = 0; kt < NCH; kt++) {
            const int s = kt & 1;
            if (kt < NCH - 1) issue(kt + 1);
            MBAR_WAIT(sb + s * 8, ph[s]);
            ph[s] ^= 1;

            const uint32_t abuf = sb + 1024 + s * PCHUNK;
            const int k0 = kt * KC;
#pragma unroll
            for (int kk = 0; kk < 4; kk++) {
                const uint32_t ac = ((uint32_t)(kk * 32) + acl) ^ axor;
                uint32_t af[2][4];
                ldsm4(af[0], abuf + arb + ac);
                ldsm4(af[1], abuf + arb + 2048 + ac);
#pragma unroll
                for (int pg = 0; pg < 3; pg++) {
                    uint32_t bf[4];
                    ldsm4(bf, wsp[pg] + (k0 + kk * 16) * 2);
                    mma_fp16(acc[2 * pg][0],     af[0], bf);
                    mma_fp16(acc[2 * pg][1],     af[1], bf);
                    mma_fp16(acc[2 * pg + 1][0], af[0], bf + 2);
                    mma_fp16(acc[2 * pg + 1][1], af[1], bf + 2);
                }
            }
            __syncthreads();
        }

        // wait for this step's GI plane (producer = concurrent k_gi)
        if (tid == 0) {
            unsigned v;
            while (true) {
                asm volatile("ld.acquire.gpu.global.u32 %0, [%1];"
                             : "=r"(v) : "l"(&g_ready[d][xt]));
                if (v) break;
                __nanosleep(200);
            }
        }
        __syncthreads();

        // ---- fused GRU epilogue ----
        const bool doOut = (t >= Cc) && (t < Tt - Cc);
        const float* __restrict__ hin = &g_h[p][d][0][0];
        float* __restrict__ hout      = &g_h[p ^ 1][d][0][0];
        char*  __restrict__ hco       = (char*)&g_hc[p ^ 1][d][0][0][0];

        const int chnk = j0 >> 6;        // constant per CTA

#pragma unroll
        for (int mi = 0; mi < 2; mi++) {
#pragma unroll
            for (int nf0 = 0; nf0 < 2; nf0++) {
                const int jj = nf0 * 8 + tg * 2;
                const int j  = j0 + jj;
                const int jc = j & 63;
                const float br0 = bh0[j],            br1 = bh0[j + 1];
                const float bz0 = bh0[HP + j],       bz1 = bh0[HP + j + 1];
                const float bn0 = bh0[2 * HP + j],   bn1 = bh0[2 * HP + j + 1];
#pragma unroll
                for (int half2i = 0; half2i < 2; half2i++) {
                    const int b  = m0w + mi * 16 + grp + half2i * 8;
                    const int ai = half2i * 2;
                    const float aR0 = acc[nf0][mi][ai],     aR1 = acc[nf0][mi][ai + 1];
                    const float aZ0 = acc[nf0 + 2][mi][ai], aZ1 = acc[nf0 + 2][mi][ai + 1];
                    const float aN0 = acc[nf0 + 4][mi][ai], aN1 = acc[nf0 + 4][mi][ai + 1];

                    const size_t gio = (size_t)(xt * Bb + b) * HP + j;
                    const float gr0 = __ldcg(&GI0[gio]);
                    const float gr1 = __ldcg(&GI0[gio + 1]);
                    const float gz0 = __ldcg(&GI0[PLANE + gio]);
                    const float gz1 = __ldcg(&GI0[PLANE + gio + 1]);
                    const float gn0 = __ldcg(&GI0[2 * PLANE + gio]);
                    const float gn1 = __ldcg(&GI0[2 * PLANE + gio + 1]);

                    const float ho0 = __ldcg(&hin[(size_t)b * HP + j]);
                    const float ho1 = __ldcg(&hin[(size_t)b * HP + j + 1]);

                    const float r0 = sigf(gr0 + aR0 + br0);
                    const float r1 = sigf(gr1 + aR1 + br1);
                    const float z0 = sigf(gz0 + aZ0 + bz0);
                    const float z1 = sigf(gz1 + aZ1 + bz1);
                    const float n0 = tanh_fast(gn0 + r0 * (aN0 + bn0));
                    const float n1 = tanh_fast(gn1 + r1 * (aN1 + bn1));
                    const float h0 = (1.0f - z0) * n0 + z0 * ho0;
                    const float h1 = (1.0f - z1) * n1 + z1 * ho1;

                    hout[(size_t)b * HP + j]     = h0;
                    hout[(size_t)b * HP + j + 1] = h1;
                    // swizzled chunked fp16 mirror
                    size_t hoff = (size_t)chnk * PCHUNK + (size_t)b * 128
                                + ((unsigned)(jc * 2) ^ ((b & 7) << 4));
                    *(__half2*)(hco + hoff) = __floats2half2_rn(h0, h1);

                    if (doOut && j < Hh) {
                        const size_t xo = (size_t)b * Tt * WIN + (size_t)xt * WIN + j;
                        const size_t oo = (size_t)b * (OUTT * OUTW) + (size_t)(t - Cc) * OUTW + d * Hh + j;
                        out[oo]     = h0 + win[xo];
                        out[oo + 1] = h1 + win[xo + 1];
                    }
                }
            }
        }

        gbar((unsigned)NCTA * (unsigned)(t + 1));
    }
}

// ---------------- launch ----------------
extern "C" void kernel_launch(void* const* d_in, const int* in_sizes, int n_in,
                              void* d_out, int out_size) {
    const float* windows = (const float*)d_in[0];
    const float* Wih_f   = (const float*)d_in[1];
    const float* Whh_f   = (const float*)d_in[2];
    const float* bih_f   = (const float*)d_in[3];
    const float* bhh_f   = (const float*)d_in[4];
    const float* Wih_b   = (const float*)d_in[5];
    const float* Whh_b   = (const float*)d_in[6];
    const float* bih_b   = (const float*)d_in[7];
    const float* bhh_b   = (const float*)d_in[8];
    float* out = (float*)d_out;

    static cudaStream_t s2 = nullptr;
    static cudaEvent_t  eA = nullptr, eB = nullptr;
    static int init_done = 0;
    if (!init_done) {
        cudaFuncSetAttribute(k_persist, cudaFuncAttributeMaxDynamicSharedMemorySize, P_SMEM);
        cudaFuncSetAttribute(k_gi, cudaFuncAttributeMaxDynamicSharedMemorySize, GI_SMEM);
        cudaStreamCreateWithFlags(&s2, cudaStreamNonBlocking);
        cudaEventCreateWithFlags(&eA, cudaEventDisableTiming);
        cudaEventCreateWithFlags(&eB, cudaEventDisableTiming);
        init_done = 1;
    }

    const int wthreads = 256;
    const int wtotal = 3 * HP * HP;
    prep_w<<<(wtotal + wthreads - 1) / wthreads, wthreads>>>(Wih_f, Whh_f, bih_f, bhh_f, 0);
    prep_w<<<(wtotal + wthreads - 1) / wthreads, wthreads>>>(Wih_b, Whh_b, bih_b, bhh_b, 1);

    const int xtotal = TB * (HP / 4);
    prep_x<<<(xtotal + 255) / 256, 256>>>(windows);

    const int htotal = 2 * 2 * Bb * HP;
    zero_h<<<(htotal + 255) / 256, 256>>>();

    // fork: k_gi concurrent with k_persist
    cudaEventRecord(eA, 0);
    cudaStreamWaitEvent(s2, eA, 0);
    k_gi<<<dim3(36, 512), 256, GI_SMEM, s2>>>();
    cudaEventRecord(eB, s2);

    k_persist<<<NCTA, 256, P_SMEM>>>(windows, out);

    cudaStreamWaitEvent(0, eB, 0);
}

// round 8
// speedup vs baseline: 2.4423x; 1.0113x over previous
#include <cuda_runtime.h>
#include <cuda_fp16.h>
#include <cstdint>

#define Hh   744
#define HP   768
#define Bb   256
#define Tt   256
#define Cc   16
#define WIN  800
#define TB   (Tt*Bb)          // 65536
#define OUTT (Tt - 2*Cc)      // 224
#define OUTW (2*Hh)           // 1488

#define NJT    48
#define JT     16
#define NCTA   (2*NJT)
#define WS_STRIDE 776         // halfs: 768 + 8 pad
#define KC     64
#define NCH    (HP/KC)        // 12
#define PCHUNK 32768          // 256 rows x 128B
#define GCHUNK 16384          // 128 rows x 128B

// ---------------- scratch ----------------
__device__ __half g_Wic[6][NCH][HP][KC];
__device__ __half g_Wh16[2][3][HP][HP];
__device__ float  g_bi[2][3][HP];
__device__ float  g_bh[2][3][HP];
__device__ __half g_Xc[NCH][TB][KC];
__device__ float  g_GI[2][3][TB][HP];
__device__ __half g_hc[2][2][NCH][Bb][KC];    // [parity][dir][chunk][b][k] swizzled
__device__ unsigned g_hcnt[2][Tt + 1][NCH];   // h-chunk readiness (target 4)
__device__ unsigned g_ready[2][Tt];
__device__ unsigned g_pcnt[2][Tt];

// ---------------- helpers ----------------
__device__ __forceinline__ float sigf(float x) { return 1.0f / (1.0f + __expf(-x)); }
__device__ __forceinline__ float tanh_fast(float x) {
    x = fminf(15.0f, fmaxf(-15.0f, x));
    float e = __expf(2.0f * x);
    return (e - 1.0f) / (e + 1.0f);
}
__device__ __forceinline__ void mma_fp16(float* c, const uint32_t* a, const uint32_t* b) {
    asm volatile(
        "mma.sync.aligned.m16n8k16.row.col.f32.f16.f16.f32 "
        "{%0,%1,%2,%3},{%4,%5,%6,%7},{%8,%9},{%0,%1,%2,%3};\n"
        : "+f"(c[0]), "+f"(c[1]), "+f"(c[2]), "+f"(c[3])
        : "r"(a[0]), "r"(a[1]), "r"(a[2]), "r"(a[3]), "r"(b[0]), "r"(b[1]));
}
__device__ __forceinline__ uint32_t s2u(const void* p) {
    return (uint32_t)__cvta_generic_to_shared(p);
}
__device__ __forceinline__ void ldsm4(uint32_t* r, uint32_t addr) {
    asm volatile("ldmatrix.sync.aligned.m8n8.x4.shared.b16 {%0,%1,%2,%3}, [%4];"
        : "=r"(r[0]), "=r"(r[1]), "=r"(r[2]), "=r"(r[3]) : "r"(addr));
}
#define MBAR_INIT(addr, cnt) \
    asm volatile("mbarrier.init.shared.b64 [%0], %1;" :: "r"(addr), "r"(cnt) : "memory")
#define MBAR_WAIT(addr, par) do { \
    asm volatile("{.reg .pred P1; WL%=: mbarrier.try_wait.parity.acquire.cta.shared::cta.b64 P1, [%0], %1, 0x989680; @P1 bra.uni WD%=; bra.uni WL%=; WD%=:}" \
        :: "r"(addr), "r"(par) : "memory"); \
} while (0)
__device__ __forceinline__ void bulk_ld(uint32_t dst, const void* src, uint32_t bytes, uint32_t mb) {
    asm volatile("cp.async.bulk.shared::cta.global.mbarrier::complete_tx::bytes [%0], [%1], %2, [%3];"
        :: "r"(dst), "l"(src), "r"(bytes), "r"(mb) : "memory");
}
__device__ __forceinline__ void expect_tx(uint32_t mb, uint32_t bytes) {
    asm volatile("mbarrier.arrive.expect_tx.shared.b64 _, [%0], %1;"
        :: "r"(mb), "r"(bytes) : "memory");
}
__device__ __forceinline__ unsigned ld_acq(const unsigned* p) {
    unsigned v;
    asm volatile("ld.acquire.gpu.global.u32 %0, [%1];" : "=r"(v) : "l"(p));
    return v;
}

// ---------------- prep kernels ----------------
__global__ void prep_w(const float* __restrict__ Wih, const float* __restrict__ Whh,
                       const float* __restrict__ bih, const float* __restrict__ bhh, int d) {
    int idx = blockIdx.x * blockDim.x + threadIdx.x;
    const int total = 3 * HP * HP;
    if (idx < total) {
        int g = idx / (HP * HP);
        int rem = idx % (HP * HP);
        int j = rem / HP;
        int k = rem % HP;
        float wi = 0.0f, wh = 0.0f;
        if (j < Hh && k < Hh) {
            wi = Wih[(size_t)(g * Hh + j) * Hh + k];
            wh = Whh[(size_t)(g * Hh + j) * Hh + k];
        }
        int dg = d * 3 + g;
        int ch = k / KC, kc = k % KC;
        size_t off = (((size_t)dg * NCH + ch) * HP + j) * 128 + (((unsigned)(kc * 2)) ^ ((j & 7) << 4));
        *(__half*)((char*)g_Wic + off) = __float2half_rn(wi);
        g_Wh16[d][g][j][k] = __float2half_rn(wh);
    }
    if (idx < 3 * HP) {
        int g = idx / HP, j = idx % HP;
        float bi = 0.0f, bh = 0.0f;
        if (j < Hh) { bi = bih[g * Hh + j]; bh = bhh[g * Hh + j]; }
        g_bi[d][g][j] = bi;
        g_bh[d][g][j] = bh;
    }
}

__global__ void prep_x(const float* __restrict__ win) {
    int idx = blockIdx.x * blockDim.x + threadIdx.x;
    const int total = TB * (HP / 4);
    if (idx >= total) return;
    int row = idx / (HP / 4);
    int kq  = idx % (HP / 4);
    int k = kq * 4;
    int t = row / Bb, b = row % Bb;
    float4 v = make_float4(0.f, 0.f, 0.f, 0.f);
    if (k < Hh) {
        v = *(const float4*)(win + (size_t)b * Tt * WIN + (size_t)t * WIN + k);
    }
    int ch = k / KC, kc = k % KC;
    size_t off = ((size_t)ch * TB + row) * 128 + (((unsigned)(kc * 2)) ^ ((row & 7) << 4));
    __half2* dst = (__half2*)((char*)g_Xc + off);
    dst[0] = __floats2half2_rn(v.x, v.y);
    dst[1] = __floats2half2_rn(v.z, v.w);
}

__global__ void zero_h() {
    int idx = blockIdx.x * blockDim.x + threadIdx.x;
    const int hcu32 = 2 * 2 * NCH * Bb * KC / 2;          // 393216
    if (idx < hcu32) ((uint32_t*)g_hc)[idx] = 0u;
    const int hcnt_total = 2 * (Tt + 1) * NCH;            // 6168
    if (idx < hcnt_total) {
        int within = idx % ((Tt + 1) * NCH);
        int step = within / NCH;
        ((unsigned*)g_hcnt)[idx] = (step == 0) ? 4u : 0u;
    }
    if (idx < 2 * Tt) { ((unsigned*)g_ready)[idx] = 0u; ((unsigned*)g_pcnt)[idx] = 0u; }
}

// ---------------- K1: GI = X @ Wih^T + bih ----------------
#define GI_SMEM (1024 + 4 * GCHUNK)
__global__ void __launch_bounds__(256, 2) k_gi() {
    extern __shared__ __align__(1024) char smem[];
    const uint32_t sb = s2u(smem);

    const int tid  = threadIdx.x;
    const int lane = tid & 31;
    const int w    = tid >> 5;
    const int grp  = lane >> 2;
    const int tg   = lane & 3;
    const int wm   = w >> 1;
    const int wn   = w & 1;

    const int bx  = blockIdx.x;
    const int d   = bx / 18;
    const int rem = bx % 18;
    const int g   = rem / 6;
    const int nt  = rem % 6;
    const int j0  = nt * 128;
    const int dg  = d * 3 + g;

    const int ti    = blockIdx.y >> 1;
    const int halfb = blockIdx.y & 1;
    const int t     = (ti & 1) ? (Tt - 1 - (ti >> 1)) : (ti >> 1);
    const int row0  = t * Bb + halfb * 128;

    if (tid == 0) { MBAR_INIT(sb, 1); MBAR_INIT(sb + 8, 1); }
    __syncthreads();

    const int arow  = wm * 32 + (lane & 15);
    const uint32_t arb  = (uint32_t)arow * 128;
    const uint32_t axor = (uint32_t)(arow & 7) << 4;
    const uint32_t acl  = (uint32_t)(lane >> 4) << 4;
    const int brow  = wn * 64 + (lane >> 4) * 8 + (lane & 7);
    const uint32_t brb  = (uint32_t)brow * 128;
    const uint32_t bxor = (uint32_t)(brow & 7) << 4;
    const uint32_t bcl  = (uint32_t)((lane >> 3) & 1) << 4;

    float acc[8][2][4];
#pragma unroll
    for (int nf = 0; nf < 8; nf++)
#pragma unroll
        for (int mi = 0; mi < 2; mi++)
#pragma unroll
            for (int i = 0; i < 4; i++) acc[nf][mi][i] = 0.0f;

    auto issue = [&](int c) {
        if (tid == 0) {
            const int s = c & 1;
            const uint32_t mb = sb + s * 8;
            expect_tx(mb, 2 * GCHUNK);
            bulk_ld(sb + 1024 + s * 2 * GCHUNK,
                    (const char*)g_Xc + ((size_t)c * TB + row0) * 128, GCHUNK, mb);
            bulk_ld(sb + 1024 + s * 2 * GCHUNK + GCHUNK,
                    (const char*)g_Wic + (((size_t)dg * NCH + c) * HP + j0) * 128, GCHUNK, mb);
        }
    };

    int ph[2] = {0, 0};
    issue(0);

    for (int kt = 0; kt < NCH; kt++) {
        const int s = kt & 1;
        if (kt < NCH - 1) issue(kt + 1);
        MBAR_WAIT(sb + s * 8, ph[s]);
        ph[s] ^= 1;

        const uint32_t abuf = sb + 1024 + s * 2 * GCHUNK;
        const uint32_t bbuf = abuf + GCHUNK;
#pragma unroll
        for (int kk = 0; kk < 4; kk++) {
            const uint32_t ac = ((uint32_t)(kk * 32) + acl) ^ axor;
            const uint32_t bc = ((uint32_t)(kk * 32) + bcl) ^ bxor;
            uint32_t af[2][4];
            ldsm4(af[0], abuf + arb + ac);
            ldsm4(af[1], abuf + arb + 2048 + ac);
#pragma unroll
            for (int p = 0; p < 4; p++) {
                uint32_t bf[4];
                ldsm4(bf, bbuf + brb + p * 2048 + bc);
                mma_fp16(acc[2 * p][0],     af[0], bf);
                mma_fp16(acc[2 * p][1],     af[1], bf);
                mma_fp16(acc[2 * p + 1][0], af[0], bf + 2);
                mma_fp16(acc[2 * p + 1][1], af[1], bf + 2);
            }
        }
        __syncthreads();
    }

    float* __restrict__ GIp = &g_GI[d][g][0][0];
    const float* __restrict__ bip = &g_bi[d][g][0];
#pragma unroll
    for (int mi = 0; mi < 2; mi++) {
#pragma unroll
        for (int nf = 0; nf < 8; nf++) {
            int r = row0 + wm * 32 + mi * 16 + grp;
            int j = j0 + wn * 64 + nf * 8 + tg * 2;
            float b0 = bip[j], b1 = bip[j + 1];
            float* a = acc[nf][mi];
            GIp[(size_t)r * HP + j]           = a[0] + b0;
            GIp[(size_t)r * HP + j + 1]       = a[1] + b1;
            GIp[(size_t)(r + 8) * HP + j]     = a[2] + b0;
            GIp[(size_t)(r + 8) * HP + j + 1] = a[3] + b1;
        }
    }

    __threadfence();
    __syncthreads();
    if (tid == 0) {
        unsigned old = atomicAdd(&g_pcnt[d][t], 1u);
        if (old == 35u) {
            asm volatile("st.release.gpu.global.u32 [%0], %1;"
                         :: "l"(&g_ready[d][t]), "r"(1u) : "memory");
        }
    }
}

// ---------------- persistent recurrent kernel ----------------
// smem: mbar0/1/2 @0/8/16 | 1024: A stages 3x32KB | 99328: Ws (74496) => 173824
#define P_ABUF  1024
#define P_WSOFF (P_ABUF + 3 * PCHUNK)
#define P_SMEM  (P_WSOFF + 48 * WS_STRIDE * 2)
__global__ void __launch_bounds__(256, 1)
k_persist(const float* __restrict__ win, float* __restrict__ out) {
    extern __shared__ __align__(1024) char smem[];
    const uint32_t sb = s2u(smem);
    __half* Ws = (__half*)(smem + P_WSOFF);

    const int tid  = threadIdx.x;
    const int lane = tid & 31;
    const int w    = tid >> 5;
    const int grp  = lane >> 2;
    const int tg   = lane & 3;
    const int m0w  = w * 32;

    const int d    = blockIdx.x / NJT;
    const int j0   = (blockIdx.x % NJT) * JT;
    const int chnk = j0 >> 6;

    if (tid == 0) { MBAR_INIT(sb, 1); MBAR_INIT(sb + 8, 1); MBAR_INIT(sb + 16, 1); }

    {
        const __half* src = &g_Wh16[d][0][0][0];
        for (int idx = tid; idx < 48 * (HP / 8); idx += 256) {
            int c = idx / (HP / 8);
            int k8 = (idx % (HP / 8)) * 8;
            int g = c / JT, jj = c % JT;
            *(uint4*)&Ws[c * WS_STRIDE + k8] =
                *(const uint4*)(src + ((size_t)g * HP + (j0 + jj)) * HP + k8);
        }
    }
    __syncthreads();

    const int arow  = m0w + (lane & 15);
    const uint32_t arb  = (uint32_t)arow * 128;
    const uint32_t axor = (uint32_t)(arow & 7) << 4;
    const uint32_t acl  = (uint32_t)(lane >> 4) << 4;

    const int b_row  = (lane >> 4) * 8 + (lane & 7);
    const int b_koff = ((lane >> 3) & 1) * 8;
    uint32_t wsp[3];
#pragma unroll
    for (int p = 0; p < 3; p++)
        wsp[p] = s2u(Ws) + ((p * 16 + b_row) * WS_STRIDE + b_koff) * 2;

    const size_t PLANE = (size_t)TB * HP;
    const float* __restrict__ GI0 = &g_GI[d][0][0][0];
    const float* __restrict__ bh0 = &g_bh[d][0][0];

    int ph[3] = {0, 0, 0};
    float hreg[16];
#pragma unroll
    for (int i = 0; i < 16; i++) hreg[i] = 0.0f;

    for (int t = 0; t < Tt; t++) {
        const int p  = t & 1;
        const int xt = (d == 0) ? t : (Tt - 1 - t);
        const char* hcbase = (const char*)&g_hc[p][d][0][0][0];

        float acc[6][2][4];
#pragma unroll
        for (int nf = 0; nf < 6; nf++)
#pragma unroll
            for (int mi = 0; mi < 2; mi++)
#pragma unroll
                for (int i = 0; i < 4; i++) acc[nf][mi][i] = 0.0f;

        int nextI = 0;
        for (int kt = 0; kt < NCH; kt++) {
            // issue ahead (depth 3), gated on per-chunk producer flags
            while (nextI < NCH && nextI <= kt + 2) {
                if (tid == 0) {
                    const unsigned* cp = &g_hcnt[d][t][nextI];
                    while (ld_acq(cp) < 4u) __nanosleep(60);
                    const int st = nextI % 3;
                    const uint32_t mb = sb + st * 8;
                    expect_tx(mb, PCHUNK);
                    bulk_ld(sb + P_ABUF + st * PCHUNK,
                            hcbase + (size_t)nextI * PCHUNK, PCHUNK, mb);
                }
                nextI++;
            }
            const int st = kt % 3;
            MBAR_WAIT(sb + st * 8, ph[st]);
            ph[st] ^= 1;

            const uint32_t abuf = sb + P_ABUF + st * PCHUNK;
            const int k0 = kt * KC;
#pragma unroll
            for (int kk = 0; kk < 4; kk++) {
                const uint32_t ac = ((uint32_t)(kk * 32) + acl) ^ axor;
                uint32_t af[2][4];
                ldsm4(af[0], abuf + arb + ac);
                ldsm4(af[1], abuf + arb + 2048 + ac);
#pragma unroll
                for (int pg = 0; pg < 3; pg++) {
                    uint32_t bf[4];
                    ldsm4(bf, wsp[pg] + (k0 + kk * 16) * 2);
                    mma_fp16(acc[2 * pg][0],     af[0], bf);
                    mma_fp16(acc[2 * pg][1],     af[1], bf);
                    mma_fp16(acc[2 * pg + 1][0], af[0], bf + 2);
                    mma_fp16(acc[2 * pg + 1][1], af[1], bf + 2);
                }
            }
            __syncthreads();
        }

        // wait for this step's GI plane
        if (tid == 0) {
            while (ld_acq(&g_ready[d][xt]) == 0u) __nanosleep(100);
        }
        __syncthreads();

        // ---- fused GRU epilogue (h state in registers) ----
        const bool doOut = (t >= Cc) && (t < Tt - Cc);
        char* __restrict__ hco = (char*)&g_hc[p ^ 1][d][0][0][0];

#pragma unroll
        for (int mi = 0; mi < 2; mi++) {
#pragma unroll
            for (int nf0 = 0; nf0 < 2; nf0++) {
                const int jj = nf0 * 8 + tg * 2;
                const int j  = j0 + jj;
                const int jc = j & 63;
                const float br0 = bh0[j],            br1 = bh0[j + 1];
                const float bz0 = bh0[HP + j],       bz1 = bh0[HP + j + 1];
                const float bn0 = bh0[2 * HP + j],   bn1 = bh0[2 * HP + j + 1];
#pragma unroll
                for (int hf = 0; hf < 2; hf++) {
                    const int unit = ((mi * 2 + nf0) * 2 + hf) * 2;
                    const int b  = m0w + mi * 16 + grp + hf * 8;
                    const int ai = hf * 2;
                    const float aR0 = acc[nf0][mi][ai],     aR1 = acc[nf0][mi][ai + 1];
                    const float aZ0 = acc[nf0 + 2][mi][ai], aZ1 = acc[nf0 + 2][mi][ai + 1];
                    const float aN0 = acc[nf0 + 4][mi][ai], aN1 = acc[nf0 + 4][mi][ai + 1];

                    const size_t gio = (size_t)(xt * Bb + b) * HP + j;
                    const float gr0 = __ldcg(&GI0[gio]);
                    const float gr1 = __ldcg(&GI0[gio + 1]);
                    const float gz0 = __ldcg(&GI0[PLANE + gio]);
                    const float gz1 = __ldcg(&GI0[PLANE + gio + 1]);
                    const float gn0 = __ldcg(&GI0[2 * PLANE + gio]);
                    const float gn1 = __ldcg(&GI0[2 * PLANE + gio + 1]);

                    const float ho0 = hreg[unit];
                    const float ho1 = hreg[unit + 1];

                    const float r0 = sigf(gr0 + aR0 + br0);
                    const float r1 = sigf(gr1 + aR1 + br1);
                    const float z0 = sigf(gz0 + aZ0 + bz0);
                    const float z1 = sigf(gz1 + aZ1 + bz1);
                    const float n0 = tanh_fast(gn0 + r0 * (aN0 + bn0));
                    const float n1 = tanh_fast(gn1 + r1 * (aN1 + bn1));
                    const float h0 = (1.0f - z0) * n0 + z0 * ho0;
                    const float h1 = (1.0f - z1) * n1 + z1 * ho1;

                    hreg[unit]     = h0;
                    hreg[unit + 1] = h1;

                    size_t hoff = (size_t)chnk * PCHUNK + (size_t)b * 128
                                + ((unsigned)(jc * 2) ^ ((b & 7) << 4));
                    *(__half2*)(hco + hoff) = __floats2half2_rn(h0, h1);

                    if (doOut && j < Hh) {
                        const size_t xo = (size_t)b * Tt * WIN + (size_t)xt * WIN + j;
                        const size_t oo = (size_t)b * (OUTT * OUTW) + (size_t)(t - Cc) * OUTW + d * Hh + j;
                        out[oo]     = h0 + win[xo];
                        out[oo + 1] = h1 + win[xo + 1];
                    }
                }
            }
        }

        // publish own h-chunk contribution for step t+1
        __threadfence();
        __syncthreads();
        if (tid == 0) {
            asm volatile("red.release.gpu.global.add.u32 [%0], 1;"
                         :: "l"(&g_hcnt[d][t + 1][chnk]) : "memory");
        }
    }
}

// ---------------- launch ----------------
extern "C" void kernel_launch(void* const* d_in, const int* in_sizes, int n_in,
                              void* d_out, int out_size) {
    const float* windows = (const float*)d_in[0];
    const float* Wih_f   = (const float*)d_in[1];
    const float* Whh_f   = (const float*)d_in[2];
    const float* bih_f   = (const float*)d_in[3];
    const float* bhh_f   = (const float*)d_in[4];
    const float* Wih_b   = (const float*)d_in[5];
    const float* Whh_b   = (const float*)d_in[6];
    const float* bih_b   = (const float*)d_in[7];
    const float* bhh_b   = (const float*)d_in[8];
    float* out = (float*)d_out;

    static cudaStream_t s2 = nullptr;
    static cudaEvent_t  eA = nullptr, eB = nullptr;
    static int init_done = 0;
    if (!init_done) {
        cudaFuncSetAttribute(k_persist, cudaFuncAttributeMaxDynamicSharedMemorySize, P_SMEM);
        cudaFuncSetAttribute(k_gi, cudaFuncAttributeMaxDynamicSharedMemorySize, GI_SMEM);
        cudaStreamCreateWithFlags(&s2, cudaStreamNonBlocking);
        cudaEventCreateWithFlags(&eA, cudaEventDisableTiming);
        cudaEventCreateWithFlags(&eB, cudaEventDisableTiming);
        init_done = 1;
    }

    // side stream: x staging (only k_gi consumes it)
    const int xtotal = TB * (HP / 4);
    prep_x<<<(xtotal + 255) / 256, 256, 0, s2>>>(windows);

    // main stream: weights + state init
    const int wthreads = 256;
    const int wtotal = 3 * HP * HP;
    prep_w<<<(wtotal + wthreads - 1) / wthreads, wthreads>>>(Wih_f, Whh_f, bih_f, bhh_f, 0);
    prep_w<<<(wtotal + wthreads - 1) / wthreads, wthreads>>>(Wih_b, Whh_b, bih_b, bhh_b, 1);
    const int ztotal = 2 * 2 * NCH * Bb * KC / 2;
    zero_h<<<(ztotal + 255) / 256, 256>>>();

    cudaEventRecord(eA, 0);
    cudaStreamWaitEvent(s2, eA, 0);
    k_gi<<<dim3(36, 512), 256, GI_SMEM, s2>>>();
    cudaEventRecord(eB, s2);

    k_persist<<<NCTA, 256, P_SMEM>>>(windows, out);

    cudaStreamWaitEvent(0, eB, 0);
}